// round 8
// baseline (speedup 1.0000x reference)
#include <cuda_runtime.h>

// ---------------- problem constants ----------------
#define Bn   4
#define Cc   64
#define DWc  128
#define Hh   256
#define Ww   256
#define HWp  65536            // H*W
#define EPSv 1e-6f
#define SCAL 2.0f

typedef unsigned long long u64;

// ---------------- packed f32x2 helpers (sm_103a FFMA2 path) ----------------
__device__ __forceinline__ u64 splat2(float w) {
    u64 r; unsigned int wi = __float_as_uint(w);
    asm("mov.b64 %0, {%1, %1};" : "=l"(r) : "r"(wi));
    return r;
}
__device__ __forceinline__ void ffma2(u64& d, u64 a, u64 b) {
    asm("fma.rn.f32x2 %0, %1, %2, %0;" : "+l"(d) : "l"(a), "l"(b));
}
__device__ __forceinline__ u64 add2(u64 a, u64 b) {
    u64 r; asm("add.rn.f32x2 %0, %1, %2;" : "=l"(r) : "l"(a), "l"(b)); return r;
}
__device__ __forceinline__ u64 mul2(u64 a, u64 b) {
    u64 r; asm("mul.rn.f32x2 %0, %1, %2;" : "=l"(r) : "l"(a), "l"(b)); return r;
}
__device__ __forceinline__ float2 unpack2(u64 v) {
    unsigned lo, hi;
    asm("mov.b64 {%0, %1}, %2;" : "=r"(lo), "=r"(hi) : "l"(v));
    float2 f; f.x = __uint_as_float(lo); f.y = __uint_as_float(hi);
    return f;
}

// ---------------- device scratch (no cudaMalloc allowed) ----------------
__device__ float g_w1  [Bn * DWc * Cc];     // conv1 eff weights (128x64)
__device__ float g_w2  [Bn * DWc * 9];      // dw3x3 eff weights
__device__ float g_wsca[Bn * Cc * Cc];
__device__ float g_w3  [Bn * Cc * Cc];
__device__ float g_w4  [Bn * DWc * Cc];
__device__ float g_w5  [Bn * Cc * Cc];
__device__ float g_t1  [Bn * DWc * HWp];    // 128 MB intermediate (conv1 out)
__device__ float g_xg  [Bn * Cc  * HWp];    // 64 MB (after simple_gate)
__device__ float g_part[Bn * Cc * 64];      // deterministic pool partials
// (k3 folded into k4 prologue; g_sca no longer needed)

// ---------------- K0: gate + effective weights ----------------
__device__ __forceinline__ void mix1x1(const float* w, const float* la, const float* lb,
                                       float* dst, int O, int e, float gs, int t) {
    const float* lae = la + e * 4 * 64;
    int N = O * 64;
    for (int idx = t; idx < N; idx += 256) {
        int o = idx >> 6, i = idx & 63;
        const float* lbo = lb + (e * O + o) * 4;
        dst[idx] = w[idx] + gs * (lbo[0] * lae[i] + lbo[1] * lae[64 + i] +
                                  lbo[2] * lae[128 + i] + lbo[3] * lae[192 + i]);
    }
}

__global__ void k_weights(const float* __restrict__ probs,
                          const float* w1, const float* la1, const float* lb1,
                          const float* w2, const float* la2, const float* lb2,
                          const float* wsca, const float* lasca, const float* lbsca,
                          const float* w3, const float* la3, const float* lb3,
                          const float* w4, const float* la4, const float* lb4,
                          const float* w5, const float* la5, const float* lb5) {
    int b = blockIdx.y, job = blockIdx.x, t = threadIdx.x;
    float p0 = probs[b * 3 + 0], p1 = probs[b * 3 + 1], p2 = probs[b * 3 + 2];
    int e = 0; float g = p0;
    if (p1 > g) { g = p1; e = 1; }
    if (p2 > g) { g = p2; e = 2; }
    float gs = g * SCAL;

    if (job == 0) {
        mix1x1(w1, la1, lb1, g_w1 + b * DWc * Cc, DWc, e, gs, t);
    } else if (job == 1) {
        for (int idx = t; idx < DWc * 9; idx += 256) {
            int row = idx / 3, col = idx - row * 3;
            const float* lbo = lb2 + (e * 384 + row) * 12;
            const float* lae = la2 + e * 36 + col;
            float acc = w2[idx];
            #pragma unroll
            for (int r = 0; r < 12; ++r) acc += gs * lbo[r] * lae[r * 3];
            g_w2[b * DWc * 9 + idx] = acc;
        }
    } else if (job == 2) {
        mix1x1(wsca, lasca, lbsca, g_wsca + b * Cc * Cc, Cc, e, gs, t);
    } else if (job == 3) {
        mix1x1(w3, la3, lb3, g_w3 + b * Cc * Cc, Cc, e, gs, t);
    } else if (job == 4) {
        mix1x1(w4, la4, lb4, g_w4 + b * DWc * Cc, DWc, e, gs, t);
    } else {
        mix1x1(w5, la5, lb5, g_w5 + b * Cc * Cc, Cc, e, gs, t);
    }
}

// ---------------- K1: LN1 + conv1 (1x1, 64->128) ----------------
// grid (512, B), block 256.  Tile = 128 px.  Thread: 8 oc x 8 px (f32x2 packed)
// Thread's pixels: {px0..px0+3, px0+64..px0+67}, px0=(t&15)*4 -> conflict-free LDS.128
// smem: xs[64][132] + ws[128][65]
#define XS1 132
__global__ void __launch_bounds__(256, 2)
k1_kernel(const float* __restrict__ inp,
          const float* __restrict__ ln1w, const float* __restrict__ ln1b,
          const float* __restrict__ b1) {
    extern __shared__ float sm[];
    float* xs = sm;                 // 64*132
    float* ws = sm + 64 * XS1;      // 128*65

    int b = blockIdx.y;
    int pix0 = blockIdx.x * 128;
    int t = threadIdx.x;

    const float* wb = g_w1 + b * DWc * Cc;
    for (int i = t; i < DWc * Cc; i += 256) ws[(i >> 6) * 65 + (i & 63)] = wb[i];

    const float* ib = inp + b * Cc * HWp + pix0;
    #pragma unroll
    for (int it = 0; it < 32; ++it) {
        int idx = it * 256 + t;
        int c = idx >> 7, p = idx & 127;
        xs[c * XS1 + p] = ib[c * HWp + p];
    }
    __syncthreads();

    // LayerNorm per pixel (warp handles 16 pixels)
    int warp = t >> 5, lane = t & 31;
    #pragma unroll
    for (int i = 0; i < 16; ++i) {
        int p = warp * 16 + i;
        float v0 = xs[lane * XS1 + p], v1 = xs[(lane + 32) * XS1 + p];
        float s = v0 + v1, q = v0 * v0 + v1 * v1;
        #pragma unroll
        for (int o = 16; o > 0; o >>= 1) {
            s += __shfl_xor_sync(0xffffffffu, s, o);
            q += __shfl_xor_sync(0xffffffffu, q, o);
        }
        float mean = s * (1.f / 64.f);
        float var  = q * (1.f / 64.f) - mean * mean;
        float inv  = rsqrtf(var + EPSv);
        xs[lane * XS1 + p]        = (v0 - mean) * inv * __ldg(&ln1w[lane])      + __ldg(&ln1b[lane]);
        xs[(lane + 32) * XS1 + p] = (v1 - mean) * inv * __ldg(&ln1w[lane + 32]) + __ldg(&ln1b[lane + 32]);
    }
    __syncthreads();

    // GEMM: 128 oc x 128 px, K=64.  Thread: 8 oc x 8 px (4 f32x2 pairs)
    int oc0 = (t >> 4) * 8, px0 = (t & 15) * 4;
    u64 acc[8][4];
    #pragma unroll
    for (int u = 0; u < 8; ++u)
        #pragma unroll
        for (int v = 0; v < 4; ++v) acc[u][v] = 0ull;

    #pragma unroll 4
    for (int k = 0; k < 64; ++k) {
        ulonglong2 xA = *(const ulonglong2*)(xs + k * XS1 + px0);
        ulonglong2 xB = *(const ulonglong2*)(xs + k * XS1 + px0 + 64);
        #pragma unroll
        for (int u = 0; u < 8; ++u) {
            u64 w2v = splat2(ws[(oc0 + u) * 65 + k]);
            ffma2(acc[u][0], w2v, xA.x);
            ffma2(acc[u][1], w2v, xA.y);
            ffma2(acc[u][2], w2v, xB.x);
            ffma2(acc[u][3], w2v, xB.y);
        }
    }

    float* ob = g_t1 + b * DWc * HWp + pix0;
    #pragma unroll
    for (int u = 0; u < 8; ++u) {
        float bias = __ldg(&b1[oc0 + u]);
        float2 p0 = unpack2(acc[u][0]), p1 = unpack2(acc[u][1]);
        float2 p2 = unpack2(acc[u][2]), p3 = unpack2(acc[u][3]);
        float4 r0 = make_float4(p0.x + bias, p0.y + bias, p1.x + bias, p1.y + bias);
        float4 r1 = make_float4(p2.x + bias, p2.y + bias, p3.x + bias, p3.y + bias);
        *(float4*)(ob + (oc0 + u) * HWp + px0)      = r0;
        *(float4*)(ob + (oc0 + u) * HWp + px0 + 64) = r1;
    }
}

// ---------------- K2: depthwise 3x3 + simple_gate + pool partials ----------------
__global__ void k2_kernel(const float* __restrict__ b2) {
    __shared__ float s0[6][256];
    __shared__ float s1[6][256];
    __shared__ float red[256];

    int b = blockIdx.z, c = blockIdx.y;
    int r0 = blockIdx.x * 4;
    int t = threadIdx.x;

    const float* t1a = g_t1 + (b * DWc + c) * HWp;
    const float* t1b = g_t1 + (b * DWc + c + 64) * HWp;

    #pragma unroll
    for (int lr = 0; lr < 6; ++lr) {
        int gr = r0 + lr - 1;
        bool ok = (gr >= 0 && gr < Hh);
        s0[lr][t] = ok ? t1a[gr * Ww + t] : 0.f;
        s1[lr][t] = ok ? t1b[gr * Ww + t] : 0.f;
    }
    __syncthreads();

    float wa[9], wb9[9];
    const float* w2a = g_w2 + (b * DWc + c) * 9;
    const float* w2b = g_w2 + (b * DWc + c + 64) * 9;
    #pragma unroll
    for (int i = 0; i < 9; ++i) { wa[i] = __ldg(&w2a[i]); wb9[i] = __ldg(&w2b[i]); }
    float biasA = __ldg(&b2[c]), biasB = __ldg(&b2[c + 64]);

    float* xgp = g_xg + (b * Cc + c) * HWp;
    float lsum = 0.f;
    int w = t;
    #pragma unroll
    for (int j = 0; j < 4; ++j) {
        float a0 = biasA, a1 = biasB;
        #pragma unroll
        for (int kh = 0; kh < 3; ++kh) {
            #pragma unroll
            for (int kw = 0; kw < 3; ++kw) {
                int col = w + kw - 1;
                bool ok = (col >= 0 && col < Ww);
                float v0 = ok ? s0[j + kh][col] : 0.f;
                float v1 = ok ? s1[j + kh][col] : 0.f;
                a0 += wa[kh * 3 + kw] * v0;
                a1 += wb9[kh * 3 + kw] * v1;
            }
        }
        float val = a0 * a1;
        xgp[(r0 + j) * Ww + w] = val;
        lsum += val;
    }

    red[t] = lsum;
    __syncthreads();
    #pragma unroll
    for (int o = 128; o > 0; o >>= 1) {
        if (t < o) red[t] += red[t + o];
        __syncthreads();
    }
    if (t == 0) g_part[(b * Cc + c) * 64 + blockIdx.x] = red[0];
}

// ---------------- K4: fused per-pixel tail (f32x2 packed matvecs) ----------------
// grid (1024, B), block 256.  Tile = 64 px.  Strides: weights 65, pixel bufs 68 (16B rows).
// Prologue also computes sca (pool mean + wsca matvec) per-CTA from g_part (k3 folded in).
#define PS4 68
__global__ void __launch_bounds__(256, 2)
k4_kernel(const float* __restrict__ inp,
          const float* __restrict__ ln2w, const float* __restrict__ ln2b,
          const float* __restrict__ bsca,
          const float* __restrict__ b3, const float* __restrict__ b4,
          const float* __restrict__ b5,
          const float* __restrict__ beta, const float* __restrict__ gamma,
          float* __restrict__ out) {
    extern __shared__ float sm[];
    float* w35s = sm;                  // 64*65 (w3 then w5)
    float* w4s  = w35s + 64 * 65;      // 128*65
    float* xsb  = w4s  + 128 * 65;     // 64*68 (x, then gate output)
    float* ysb  = xsb  + 64 * PS4;     // 64*68 (y = residual mid)
    float* zsb  = ysb  + 64 * PS4;     // 64*68 (ln2 output)
    __shared__ float s_pool[64];
    __shared__ float s_sca[64];

    int b = blockIdx.y;
    int pix0 = blockIdx.x * 64;
    int t = threadIdx.x;

    {
        const float* w3g = g_w3 + b * Cc * Cc;
        for (int i = t; i < Cc * Cc; i += 256) w35s[(i >> 6) * 65 + (i & 63)] = w3g[i];
        const float* w4g = g_w4 + b * DWc * Cc;
        for (int i = t; i < DWc * Cc; i += 256) w4s[(i >> 6) * 65 + (i & 63)] = w4g[i];
    }
    // pool mean from partials (k3 fold, part 1)
    if (t < 64) {
        float s = 0.f;
        const float4* pp = (const float4*)(g_part + (b * Cc + t) * 64);
        #pragma unroll
        for (int k = 0; k < 16; ++k) {
            float4 v = pp[k];
            s += (v.x + v.y) + (v.z + v.w);
        }
        s_pool[t] = s * (1.f / (float)HWp);
    }
    __syncthreads();
    // sca matvec (k3 fold, part 2)
    if (t < 64) {
        const float* wr = g_wsca + b * Cc * Cc + t * Cc;
        float acc = __ldg(&bsca[t]);
        #pragma unroll
        for (int i = 0; i < 64; ++i) acc += wr[i] * s_pool[i];
        s_sca[t] = acc;
    }
    __syncthreads();

    const float* xgb = g_xg + b * Cc * HWp + pix0;
    const float* ib  = inp  + b * Cc * HWp + pix0;
    #pragma unroll
    for (int it = 0; it < 16; ++it) {
        int idx = it * 256 + t;
        int c = idx >> 6, p = idx & 63;
        float sc = s_sca[c];
        xsb[c * PS4 + p] = xgb[c * HWp + p] * sc;
        ysb[c * PS4 + p] = ib[c * HWp + p];
    }
    __syncthreads();

    int tg = t >> 4, px0 = (t & 15) * 4;

    // matvec1: conv3 (64x64); thread 4 oc x 4 px (2 pairs). y = inp + (t3+bias)*beta
    {
        int oc0 = tg * 4;
        u64 a1[4][2];
        #pragma unroll
        for (int u = 0; u < 4; ++u) { a1[u][0] = 0ull; a1[u][1] = 0ull; }
        #pragma unroll 4
        for (int k = 0; k < 64; ++k) {
            ulonglong2 xp = *(const ulonglong2*)(xsb + k * PS4 + px0);
            #pragma unroll
            for (int u = 0; u < 4; ++u) {
                u64 w2v = splat2(w35s[(oc0 + u) * 65 + k]);
                ffma2(a1[u][0], w2v, xp.x);
                ffma2(a1[u][1], w2v, xp.y);
            }
        }
        #pragma unroll
        for (int u = 0; u < 4; ++u) {
            int o = oc0 + u;
            float bt = __ldg(&beta[o]);
            float bias = __ldg(&b3[o]);
            float2 p0 = unpack2(a1[u][0]), p1 = unpack2(a1[u][1]);
            float4* yv = (float4*)(ysb + o * PS4 + px0);
            float4 y = *yv;
            y.x += (p0.x + bias) * bt;
            y.y += (p0.y + bias) * bt;
            y.z += (p1.x + bias) * bt;
            y.w += (p1.y + bias) * bt;
            *yv = y;
        }
    }
    __syncthreads();

    // LN2: ysb -> zsb (warp per 8 pixels)
    {
        int warp = t >> 5, lane = t & 31;
        #pragma unroll
        for (int i = 0; i < 8; ++i) {
            int p = warp * 8 + i;
            float v0 = ysb[lane * PS4 + p], v1 = ysb[(lane + 32) * PS4 + p];
            float s = v0 + v1, q = v0 * v0 + v1 * v1;
            #pragma unroll
            for (int o = 16; o > 0; o >>= 1) {
                s += __shfl_xor_sync(0xffffffffu, s, o);
                q += __shfl_xor_sync(0xffffffffu, q, o);
            }
            float mean = s * (1.f / 64.f);
            float var  = q * (1.f / 64.f) - mean * mean;
            float inv  = rsqrtf(var + EPSv);
            zsb[lane * PS4 + p]        = (v0 - mean) * inv * __ldg(&ln2w[lane])      + __ldg(&ln2b[lane]);
            zsb[(lane + 32) * PS4 + p] = (v1 - mean) * inv * __ldg(&ln2w[lane + 32]) + __ldg(&ln2b[lane + 32]);
        }
    }
    // reload w35s with w5 (w3 fully consumed; all threads past the syncs above)
    {
        const float* w5g = g_w5 + b * Cc * Cc;
        for (int i = t; i < Cc * Cc; i += 256) w35s[(i >> 6) * 65 + (i & 63)] = w5g[i];
    }
    __syncthreads();

    // matvec2: conv4 (128x64) + simple_gate. oc = tg + 16*j keeps gate pairs in-thread.
    {
        u64 a2[8][2];
        #pragma unroll
        for (int j = 0; j < 8; ++j) { a2[j][0] = 0ull; a2[j][1] = 0ull; }
        #pragma unroll 4
        for (int k = 0; k < 64; ++k) {
            ulonglong2 zp = *(const ulonglong2*)(zsb + k * PS4 + px0);
            #pragma unroll
            for (int j = 0; j < 8; ++j) {
                u64 w2v = splat2(w4s[(tg + 16 * j) * 65 + k]);
                ffma2(a2[j][0], w2v, zp.x);
                ffma2(a2[j][1], w2v, zp.y);
            }
        }
        #pragma unroll
        for (int j = 0; j < 4; ++j) {
            int o = tg + 16 * j;
            u64 bl = splat2(__ldg(&b4[o]));
            u64 bh = splat2(__ldg(&b4[o + 64]));
            ulonglong2 gv;
            gv.x = mul2(add2(a2[j][0], bl), add2(a2[j + 4][0], bh));
            gv.y = mul2(add2(a2[j][1], bl), add2(a2[j + 4][1], bh));
            *(ulonglong2*)(xsb + o * PS4 + px0) = gv;
        }
    }
    __syncthreads();

    // matvec3: conv5 (64x64);  out = y + (t5+bias)*gamma
    {
        int oc0 = tg * 4;
        u64 a3[4][2];
        #pragma unroll
        for (int u = 0; u < 4; ++u) { a3[u][0] = 0ull; a3[u][1] = 0ull; }
        #pragma unroll 4
        for (int k = 0; k < 64; ++k) {
            ulonglong2 gp = *(const ulonglong2*)(xsb + k * PS4 + px0);
            #pragma unroll
            for (int u = 0; u < 4; ++u) {
                u64 w2v = splat2(w35s[(oc0 + u) * 65 + k]);
                ffma2(a3[u][0], w2v, gp.x);
                ffma2(a3[u][1], w2v, gp.y);
            }
        }
        float* ob = out + b * Cc * HWp + pix0 + px0;
        #pragma unroll
        for (int u = 0; u < 4; ++u) {
            int o = oc0 + u;
            float gm = __ldg(&gamma[o]);
            float bias = __ldg(&b5[o]);
            float2 p0 = unpack2(a3[u][0]), p1 = unpack2(a3[u][1]);
            float4 yv = *(const float4*)(ysb + o * PS4 + px0);
            float4 r;
            r.x = yv.x + (p0.x + bias) * gm;
            r.y = yv.y + (p0.y + bias) * gm;
            r.z = yv.z + (p1.x + bias) * gm;
            r.w = yv.w + (p1.y + bias) * gm;
            *(float4*)(ob + o * HWp) = r;
        }
    }
}

// ---------------- launch ----------------
extern "C" void kernel_launch(void* const* d_in, const int* in_sizes, int n_in,
                              void* d_out, int out_size) {
    const float* inp   = (const float*)d_in[0];
    const float* probs = (const float*)d_in[1];
    const float* ln1w  = (const float*)d_in[2];
    const float* ln1b  = (const float*)d_in[3];
    const float* ln2w  = (const float*)d_in[4];
    const float* ln2b  = (const float*)d_in[5];
    const float* w1    = (const float*)d_in[6];
    const float* b1    = (const float*)d_in[7];
    const float* la1   = (const float*)d_in[8];
    const float* lb1   = (const float*)d_in[9];
    const float* w2    = (const float*)d_in[10];
    const float* b2    = (const float*)d_in[11];
    const float* la2   = (const float*)d_in[12];
    const float* lb2   = (const float*)d_in[13];
    const float* wsca  = (const float*)d_in[14];
    const float* bsca  = (const float*)d_in[15];
    const float* lasca = (const float*)d_in[16];
    const float* lbsca = (const float*)d_in[17];
    const float* w3    = (const float*)d_in[18];
    const float* b3    = (const float*)d_in[19];
    const float* la3   = (const float*)d_in[20];
    const float* lb3   = (const float*)d_in[21];
    const float* w4    = (const float*)d_in[22];
    const float* b4    = (const float*)d_in[23];
    const float* la4   = (const float*)d_in[24];
    const float* lb4   = (const float*)d_in[25];
    const float* w5    = (const float*)d_in[26];
    const float* b5    = (const float*)d_in[27];
    const float* la5   = (const float*)d_in[28];
    const float* lb5   = (const float*)d_in[29];
    const float* beta  = (const float*)d_in[30];
    const float* gamma = (const float*)d_in[31];
    float* out = (float*)d_out;

    const int SM1 = (64 * XS1 + 128 * 65) * (int)sizeof(float);               // 67,072
    const int SM4 = (64 * 65 + 128 * 65 + 3 * 64 * PS4) * (int)sizeof(float); // 102,144
    cudaFuncSetAttribute(k1_kernel, cudaFuncAttributeMaxDynamicSharedMemorySize, SM1);
    cudaFuncSetAttribute(k4_kernel, cudaFuncAttributeMaxDynamicSharedMemorySize, SM4);

    k_weights<<<dim3(6, Bn), 256>>>(probs,
                                    w1, la1, lb1, w2, la2, lb2,
                                    wsca, lasca, lbsca, w3, la3, lb3,
                                    w4, la4, lb4, w5, la5, lb5);
    k1_kernel<<<dim3(HWp / 128, Bn), 256, SM1>>>(inp, ln1w, ln1b, b1);
    k2_kernel<<<dim3(Hh / 4, Cc, Bn), 256>>>(b2);
    k4_kernel<<<dim3(HWp / 64, Bn), 256, SM4>>>(inp, ln2w, ln2b, bsca, b3, b4, b5, beta, gamma, out);
}

// round 9
// speedup vs baseline: 1.0538x; 1.0538x over previous
#include <cuda_runtime.h>

// ---------------- problem constants ----------------
#define Bn   4
#define Cc   64
#define DWc  128
#define Hh   256
#define Ww   256
#define HWp  65536            // H*W
#define EPSv 1e-6f
#define SCAL 2.0f

typedef unsigned long long u64;

// ---------------- packed f32x2 helpers (sm_103a FFMA2 path) ----------------
__device__ __forceinline__ u64 splat2(float w) {
    u64 r; unsigned int wi = __float_as_uint(w);
    asm("mov.b64 %0, {%1, %1};" : "=l"(r) : "r"(wi));
    return r;
}
__device__ __forceinline__ void ffma2(u64& d, u64 a, u64 b) {
    asm("fma.rn.f32x2 %0, %1, %2, %0;" : "+l"(d) : "l"(a), "l"(b));
}
__device__ __forceinline__ u64 add2(u64 a, u64 b) {
    u64 r; asm("add.rn.f32x2 %0, %1, %2;" : "=l"(r) : "l"(a), "l"(b)); return r;
}
__device__ __forceinline__ u64 mul2(u64 a, u64 b) {
    u64 r; asm("mul.rn.f32x2 %0, %1, %2;" : "=l"(r) : "l"(a), "l"(b)); return r;
}
__device__ __forceinline__ float2 unpack2(u64 v) {
    unsigned lo, hi;
    asm("mov.b64 {%0, %1}, %2;" : "=r"(lo), "=r"(hi) : "l"(v));
    float2 f; f.x = __uint_as_float(lo); f.y = __uint_as_float(hi);
    return f;
}

// ---------------- device scratch (no cudaMalloc allowed) ----------------
__device__ float g_w1  [Bn * DWc * Cc];
__device__ float g_w2  [Bn * DWc * 9];
__device__ float g_wsca[Bn * Cc * Cc];
__device__ float g_w3  [Bn * Cc * Cc];
__device__ float g_w4  [Bn * DWc * Cc];
__device__ float g_w5  [Bn * Cc * Cc];
__device__ float g_t1  [Bn * DWc * HWp];    // conv1 out
__device__ float g_xg  [Bn * Cc  * HWp];    // after simple_gate
__device__ float g_part[Bn * Cc * 64];      // deterministic pool partials

// ---------------- K0: gate + effective weights ----------------
__device__ __forceinline__ void mix1x1(const float* w, const float* la, const float* lb,
                                       float* dst, int O, int e, float gs, int t) {
    const float* lae = la + e * 4 * 64;
    int N = O * 64;
    for (int idx = t; idx < N; idx += 256) {
        int o = idx >> 6, i = idx & 63;
        const float* lbo = lb + (e * O + o) * 4;
        dst[idx] = w[idx] + gs * (lbo[0] * lae[i] + lbo[1] * lae[64 + i] +
                                  lbo[2] * lae[128 + i] + lbo[3] * lae[192 + i]);
    }
}

__global__ void k_weights(const float* __restrict__ probs,
                          const float* w1, const float* la1, const float* lb1,
                          const float* w2, const float* la2, const float* lb2,
                          const float* wsca, const float* lasca, const float* lbsca,
                          const float* w3, const float* la3, const float* lb3,
                          const float* w4, const float* la4, const float* lb4,
                          const float* w5, const float* la5, const float* lb5) {
    int b = blockIdx.y, job = blockIdx.x, t = threadIdx.x;
    float p0 = probs[b * 3 + 0], p1 = probs[b * 3 + 1], p2 = probs[b * 3 + 2];
    int e = 0; float g = p0;
    if (p1 > g) { g = p1; e = 1; }
    if (p2 > g) { g = p2; e = 2; }
    float gs = g * SCAL;

    if (job == 0) {
        mix1x1(w1, la1, lb1, g_w1 + b * DWc * Cc, DWc, e, gs, t);
    } else if (job == 1) {
        for (int idx = t; idx < DWc * 9; idx += 256) {
            int row = idx / 3, col = idx - row * 3;
            const float* lbo = lb2 + (e * 384 + row) * 12;
            const float* lae = la2 + e * 36 + col;
            float acc = w2[idx];
            #pragma unroll
            for (int r = 0; r < 12; ++r) acc += gs * lbo[r] * lae[r * 3];
            g_w2[b * DWc * 9 + idx] = acc;
        }
    } else if (job == 2) {
        mix1x1(wsca, lasca, lbsca, g_wsca + b * Cc * Cc, Cc, e, gs, t);
    } else if (job == 3) {
        mix1x1(w3, la3, lb3, g_w3 + b * Cc * Cc, Cc, e, gs, t);
    } else if (job == 4) {
        mix1x1(w4, la4, lb4, g_w4 + b * DWc * Cc, DWc, e, gs, t);
    } else {
        mix1x1(w5, la5, lb5, g_w5 + b * Cc * Cc, Cc, e, gs, t);
    }
}

// ---------------- K1: LN1 + conv1 (1x1, 64->128) ----------------
// grid (512, B), block 256.  Tile = 128 px.  Thread: 8 oc x 8 px (f32x2 packed)
// Weight stride 68 (16B rows) for float2 weight loads, k chunked by 2.
#define XS1 132
#define WS  68
__global__ void __launch_bounds__(256, 2)
k1_kernel(const float* __restrict__ inp,
          const float* __restrict__ ln1w, const float* __restrict__ ln1b,
          const float* __restrict__ b1) {
    extern __shared__ float sm[];
    float* xs = sm;                 // 64*132
    float* ws = sm + 64 * XS1;      // 128*68
    __shared__ float sred[256], qred[256], smean[128], sinv[128];
    __shared__ float lnws[64], lnbs[64];

    int b = blockIdx.y;
    int pix0 = blockIdx.x * 128;
    int t = threadIdx.x;

    const float* wb = g_w1 + b * DWc * Cc;
    for (int i = t; i < DWc * Cc; i += 256) ws[(i >> 6) * WS + (i & 63)] = wb[i];
    if (t < 64) { lnws[t] = ln1w[t]; lnbs[t] = ln1b[t]; }

    const float* ib = inp + b * Cc * HWp + pix0;
    #pragma unroll
    for (int it = 0; it < 32; ++it) {
        int idx = it * 256 + t;
        int c = idx >> 7, p = idx & 127;
        xs[c * XS1 + p] = ib[c * HWp + p];
    }
    __syncthreads();

    // LN1, conflict-free column access: thread -> pixel p = t&127, half hh = t>>7
    {
        int p = t & 127, hh = t >> 7;
        float s = 0.f, qs = 0.f;
        #pragma unroll
        for (int c = 0; c < 32; ++c) {
            float v = xs[(hh * 32 + c) * XS1 + p];
            s += v; qs += v * v;
        }
        sred[t] = s; qred[t] = qs;
        __syncthreads();
        if (t < 128) {
            float S = sred[t] + sred[t + 128];
            float Q = qred[t] + qred[t + 128];
            float mean = S * (1.f / 64.f);
            float var  = Q * (1.f / 64.f) - mean * mean;
            smean[t] = mean;
            sinv[t]  = rsqrtf(var + EPSv);
        }
        __syncthreads();
        float mean = smean[p], inv = sinv[p];
        #pragma unroll
        for (int c = 0; c < 32; ++c) {
            int ch = hh * 32 + c;
            float v = xs[ch * XS1 + p];
            xs[ch * XS1 + p] = (v - mean) * inv * lnws[ch] + lnbs[ch];
        }
    }
    __syncthreads();

    // GEMM: 128 oc x 128 px, K=64.  Thread: 8 oc x 8 px. k chunked by 2, float2 weights.
    int oc0 = (t >> 4) * 8, px0 = (t & 15) * 4;
    u64 acc[8][4];
    #pragma unroll
    for (int u = 0; u < 8; ++u)
        #pragma unroll
        for (int v = 0; v < 4; ++v) acc[u][v] = 0ull;

    #pragma unroll 2
    for (int kc = 0; kc < 64; kc += 2) {
        ulonglong2 xA0 = *(const ulonglong2*)(xs + kc * XS1 + px0);
        ulonglong2 xB0 = *(const ulonglong2*)(xs + kc * XS1 + px0 + 64);
        ulonglong2 xA1 = *(const ulonglong2*)(xs + (kc + 1) * XS1 + px0);
        ulonglong2 xB1 = *(const ulonglong2*)(xs + (kc + 1) * XS1 + px0 + 64);
        #pragma unroll
        for (int u = 0; u < 8; ++u) {
            float2 wv = *(const float2*)(ws + (oc0 + u) * WS + kc);
            u64 w0 = splat2(wv.x), w1s = splat2(wv.y);
            ffma2(acc[u][0], w0, xA0.x);
            ffma2(acc[u][1], w0, xA0.y);
            ffma2(acc[u][2], w0, xB0.x);
            ffma2(acc[u][3], w0, xB0.y);
            ffma2(acc[u][0], w1s, xA1.x);
            ffma2(acc[u][1], w1s, xA1.y);
            ffma2(acc[u][2], w1s, xB1.x);
            ffma2(acc[u][3], w1s, xB1.y);
        }
    }

    float* ob = g_t1 + b * DWc * HWp + pix0;
    #pragma unroll
    for (int u = 0; u < 8; ++u) {
        float bias = __ldg(&b1[oc0 + u]);
        float2 p0 = unpack2(acc[u][0]), p1 = unpack2(acc[u][1]);
        float2 p2 = unpack2(acc[u][2]), p3 = unpack2(acc[u][3]);
        float4 r0 = make_float4(p0.x + bias, p0.y + bias, p1.x + bias, p1.y + bias);
        float4 r1 = make_float4(p2.x + bias, p2.y + bias, p3.x + bias, p3.y + bias);
        *(float4*)(ob + (oc0 + u) * HWp + px0)      = r0;
        *(float4*)(ob + (oc0 + u) * HWp + px0 + 64) = r1;
    }
}

// ---------------- K2: depthwise 3x3 + simple_gate + pool partials ----------------
__global__ void k2_kernel(const float* __restrict__ b2) {
    __shared__ float s0[6][256];
    __shared__ float s1[6][256];
    __shared__ float red[256];

    int b = blockIdx.z, c = blockIdx.y;
    int r0 = blockIdx.x * 4;
    int t = threadIdx.x;

    const float* t1a = g_t1 + (b * DWc + c) * HWp;
    const float* t1b = g_t1 + (b * DWc + c + 64) * HWp;

    #pragma unroll
    for (int lr = 0; lr < 6; ++lr) {
        int gr = r0 + lr - 1;
        bool ok = (gr >= 0 && gr < Hh);
        s0[lr][t] = ok ? t1a[gr * Ww + t] : 0.f;
        s1[lr][t] = ok ? t1b[gr * Ww + t] : 0.f;
    }
    __syncthreads();

    float wa[9], wb9[9];
    const float* w2a = g_w2 + (b * DWc + c) * 9;
    const float* w2b = g_w2 + (b * DWc + c + 64) * 9;
    #pragma unroll
    for (int i = 0; i < 9; ++i) { wa[i] = __ldg(&w2a[i]); wb9[i] = __ldg(&w2b[i]); }
    float biasA = __ldg(&b2[c]), biasB = __ldg(&b2[c + 64]);

    float* xgp = g_xg + (b * Cc + c) * HWp;
    float lsum = 0.f;
    int w = t;
    #pragma unroll
    for (int j = 0; j < 4; ++j) {
        float a0 = biasA, a1 = biasB;
        #pragma unroll
        for (int kh = 0; kh < 3; ++kh) {
            #pragma unroll
            for (int kw = 0; kw < 3; ++kw) {
                int col = w + kw - 1;
                bool ok = (col >= 0 && col < Ww);
                float v0 = ok ? s0[j + kh][col] : 0.f;
                float v1 = ok ? s1[j + kh][col] : 0.f;
                a0 += wa[kh * 3 + kw] * v0;
                a1 += wb9[kh * 3 + kw] * v1;
            }
        }
        float val = a0 * a1;
        xgp[(r0 + j) * Ww + w] = val;
        lsum += val;
    }

    red[t] = lsum;
    __syncthreads();
    #pragma unroll
    for (int o = 128; o > 0; o >>= 1) {
        if (t < o) red[t] += red[t + o];
        __syncthreads();
    }
    if (t == 0) g_part[(b * Cc + c) * 64 + blockIdx.x] = red[0];
}

// ---------------- K4: fused per-pixel tail ----------------
// grid (1024, B), block 256.  Tile = 64 px.
// Weight stride WS=68 (float4 weight loads, k chunked by 4); pixel stride PS4=68.
// Buffers: xsb = x for conv3, then LN2 output; ysb = residual y; gsb = gate output.
#define PS4 68
__global__ void __launch_bounds__(256, 2)
k4_kernel(const float* __restrict__ inp,
          const float* __restrict__ ln2w, const float* __restrict__ ln2b,
          const float* __restrict__ bsca,
          const float* __restrict__ b3, const float* __restrict__ b4,
          const float* __restrict__ b5,
          const float* __restrict__ beta, const float* __restrict__ gamma,
          float* __restrict__ out) {
    extern __shared__ float sm[];
    float* w35s = sm;                  // 64*68 (w3 then w5)
    float* w4s  = w35s + 64 * WS;      // 128*68
    float* xsb  = w4s  + 128 * WS;     // 64*68
    float* ysb  = xsb  + 64 * PS4;     // 64*68
    float* gsb  = ysb  + 64 * PS4;     // 64*68
    __shared__ float sred[256], qred[256], smean[64], sinv[64];
    __shared__ float lnws[64], lnbs[64];
    __shared__ float s_pool[64], s_sca[64];

    int b = blockIdx.y;
    int pix0 = blockIdx.x * 64;
    int t = threadIdx.x;

    {
        const float* w3g = g_w3 + b * Cc * Cc;
        for (int i = t; i < Cc * Cc; i += 256) w35s[(i >> 6) * WS + (i & 63)] = w3g[i];
        const float* w4g = g_w4 + b * DWc * Cc;
        for (int i = t; i < DWc * Cc; i += 256) w4s[(i >> 6) * WS + (i & 63)] = w4g[i];
    }
    if (t < 64) { lnws[t] = ln2w[t]; lnbs[t] = ln2b[t]; }
    // pool mean from partials (k3 fold)
    if (t < 64) {
        float s = 0.f;
        const float4* pp = (const float4*)(g_part + (b * Cc + t) * 64);
        #pragma unroll
        for (int k = 0; k < 16; ++k) {
            float4 v = pp[k];
            s += (v.x + v.y) + (v.z + v.w);
        }
        s_pool[t] = s * (1.f / (float)HWp);
    }
    __syncthreads();
    if (t < 64) {
        const float* wr = g_wsca + b * Cc * Cc + t * Cc;
        float acc = __ldg(&bsca[t]);
        #pragma unroll
        for (int i = 0; i < 64; ++i) acc += wr[i] * s_pool[i];
        s_sca[t] = acc;
    }
    __syncthreads();

    const float* xgb = g_xg + b * Cc * HWp + pix0;
    const float* ib  = inp  + b * Cc * HWp + pix0;
    #pragma unroll
    for (int it = 0; it < 16; ++it) {
        int idx = it * 256 + t;
        int c = idx >> 6, p = idx & 63;
        float sc = s_sca[c];
        xsb[c * PS4 + p] = xgb[c * HWp + p] * sc;
        ysb[c * PS4 + p] = ib[c * HWp + p];
    }
    __syncthreads();

    int tg = t >> 4, px0 = (t & 15) * 4;

    // matvec1: conv3 (64x64); thread 4 oc x 4 px. k chunk 4, float4 weights.
    // y = inp + (t3+bias)*beta
    {
        int oc0 = tg * 4;
        u64 a1[4][2];
        #pragma unroll
        for (int u = 0; u < 4; ++u) { a1[u][0] = 0ull; a1[u][1] = 0ull; }
        #pragma unroll 2
        for (int kc = 0; kc < 64; kc += 4) {
            ulonglong2 x0 = *(const ulonglong2*)(xsb + (kc + 0) * PS4 + px0);
            ulonglong2 x1 = *(const ulonglong2*)(xsb + (kc + 1) * PS4 + px0);
            ulonglong2 x2 = *(const ulonglong2*)(xsb + (kc + 2) * PS4 + px0);
            ulonglong2 x3 = *(const ulonglong2*)(xsb + (kc + 3) * PS4 + px0);
            #pragma unroll
            for (int u = 0; u < 4; ++u) {
                float4 wv = *(const float4*)(w35s + (oc0 + u) * WS + kc);
                u64 w0 = splat2(wv.x), w1s = splat2(wv.y);
                u64 w2s = splat2(wv.z), w3s = splat2(wv.w);
                ffma2(a1[u][0], w0, x0.x);  ffma2(a1[u][1], w0, x0.y);
                ffma2(a1[u][0], w1s, x1.x); ffma2(a1[u][1], w1s, x1.y);
                ffma2(a1[u][0], w2s, x2.x); ffma2(a1[u][1], w2s, x2.y);
                ffma2(a1[u][0], w3s, x3.x); ffma2(a1[u][1], w3s, x3.y);
            }
        }
        #pragma unroll
        for (int u = 0; u < 4; ++u) {
            int o = oc0 + u;
            float bt = __ldg(&beta[o]);
            float bias = __ldg(&b3[o]);
            float2 p0 = unpack2(a1[u][0]), p1 = unpack2(a1[u][1]);
            float4* yv = (float4*)(ysb + o * PS4 + px0);
            float4 y = *yv;
            y.x += (p0.x + bias) * bt;
            y.y += (p0.y + bias) * bt;
            y.z += (p1.x + bias) * bt;
            y.w += (p1.y + bias) * bt;
            *yv = y;
        }
    }
    __syncthreads();

    // LN2 (conflict-free): thread -> pixel p = t&63, quarter qq = t>>6 (16 channels).
    // Output -> xsb (dead after matvec1).  w5 reload overlapped before the barrier.
    {
        int p = t & 63, qq = t >> 6;
        float s = 0.f, qs = 0.f;
        #pragma unroll
        for (int c = 0; c < 16; ++c) {
            float v = ysb[(qq * 16 + c) * PS4 + p];
            s += v; qs += v * v;
        }
        sred[t] = s; qred[t] = qs;
        __syncthreads();
        if (t < 64) {
            float S = sred[t] + sred[t + 64] + sred[t + 128] + sred[t + 192];
            float Q = qred[t] + qred[t + 64] + qred[t + 128] + qred[t + 192];
            float mean = S * (1.f / 64.f);
            float var  = Q * (1.f / 64.f) - mean * mean;
            smean[t] = mean;
            sinv[t]  = rsqrtf(var + EPSv);
        }
        // reload w35s with w5 (w3 fully consumed)
        const float* w5g = g_w5 + b * Cc * Cc;
        for (int i = t; i < Cc * Cc; i += 256) w35s[(i >> 6) * WS + (i & 63)] = w5g[i];
        __syncthreads();
        float mean = smean[p], inv = sinv[p];
        #pragma unroll
        for (int c = 0; c < 16; ++c) {
            int ch = qq * 16 + c;
            float v = ysb[ch * PS4 + p];
            xsb[ch * PS4 + p] = (v - mean) * inv * lnws[ch] + lnbs[ch];
        }
    }
    __syncthreads();

    // matvec2: conv4 (128x64) + simple_gate. oc = tg + 16*j keeps gate pairs in-thread.
    {
        u64 a2[8][2];
        #pragma unroll
        for (int j = 0; j < 8; ++j) { a2[j][0] = 0ull; a2[j][1] = 0ull; }
        for (int kc = 0; kc < 64; kc += 4) {
            ulonglong2 z0 = *(const ulonglong2*)(xsb + (kc + 0) * PS4 + px0);
            ulonglong2 z1 = *(const ulonglong2*)(xsb + (kc + 1) * PS4 + px0);
            ulonglong2 z2 = *(const ulonglong2*)(xsb + (kc + 2) * PS4 + px0);
            ulonglong2 z3 = *(const ulonglong2*)(xsb + (kc + 3) * PS4 + px0);
            #pragma unroll
            for (int j = 0; j < 8; ++j) {
                float4 wv = *(const float4*)(w4s + (tg + 16 * j) * WS + kc);
                u64 w0 = splat2(wv.x), w1s = splat2(wv.y);
                u64 w2s = splat2(wv.z), w3s = splat2(wv.w);
                ffma2(a2[j][0], w0, z0.x);  ffma2(a2[j][1], w0, z0.y);
                ffma2(a2[j][0], w1s, z1.x); ffma2(a2[j][1], w1s, z1.y);
                ffma2(a2[j][0], w2s, z2.x); ffma2(a2[j][1], w2s, z2.y);
                ffma2(a2[j][0], w3s, z3.x); ffma2(a2[j][1], w3s, z3.y);
            }
        }
        #pragma unroll
        for (int j = 0; j < 4; ++j) {
            int o = tg + 16 * j;
            u64 bl = splat2(__ldg(&b4[o]));
            u64 bh = splat2(__ldg(&b4[o + 64]));
            ulonglong2 gv;
            gv.x = mul2(add2(a2[j][0], bl), add2(a2[j + 4][0], bh));
            gv.y = mul2(add2(a2[j][1], bl), add2(a2[j + 4][1], bh));
            *(ulonglong2*)(gsb + o * PS4 + px0) = gv;
        }
    }
    __syncthreads();

    // matvec3: conv5 (64x64);  out = y + (t5+bias)*gamma
    {
        int oc0 = tg * 4;
        u64 a3[4][2];
        #pragma unroll
        for (int u = 0; u < 4; ++u) { a3[u][0] = 0ull; a3[u][1] = 0ull; }
        #pragma unroll 2
        for (int kc = 0; kc < 64; kc += 4) {
            ulonglong2 g0 = *(const ulonglong2*)(gsb + (kc + 0) * PS4 + px0);
            ulonglong2 g1 = *(const ulonglong2*)(gsb + (kc + 1) * PS4 + px0);
            ulonglong2 g2 = *(const ulonglong2*)(gsb + (kc + 2) * PS4 + px0);
            ulonglong2 g3 = *(const ulonglong2*)(gsb + (kc + 3) * PS4 + px0);
            #pragma unroll
            for (int u = 0; u < 4; ++u) {
                float4 wv = *(const float4*)(w35s + (oc0 + u) * WS + kc);
                u64 w0 = splat2(wv.x), w1s = splat2(wv.y);
                u64 w2s = splat2(wv.z), w3s = splat2(wv.w);
                ffma2(a3[u][0], w0, g0.x);  ffma2(a3[u][1], w0, g0.y);
                ffma2(a3[u][0], w1s, g1.x); ffma2(a3[u][1], w1s, g1.y);
                ffma2(a3[u][0], w2s, g2.x); ffma2(a3[u][1], w2s, g2.y);
                ffma2(a3[u][0], w3s, g3.x); ffma2(a3[u][1], w3s, g3.y);
            }
        }
        float* ob = out + b * Cc * HWp + pix0 + px0;
        #pragma unroll
        for (int u = 0; u < 4; ++u) {
            int o = oc0 + u;
            float gm = __ldg(&gamma[o]);
            float bias = __ldg(&b5[o]);
            float2 p0 = unpack2(a3[u][0]), p1 = unpack2(a3[u][1]);
            float4 yv = *(const float4*)(ysb + o * PS4 + px0);
            float4 r;
            r.x = yv.x + (p0.x + bias) * gm;
            r.y = yv.y + (p0.y + bias) * gm;
            r.z = yv.z + (p1.x + bias) * gm;
            r.w = yv.w + (p1.y + bias) * gm;
            *(float4*)(ob + o * HWp) = r;
        }
    }
}

// ---------------- launch ----------------
extern "C" void kernel_launch(void* const* d_in, const int* in_sizes, int n_in,
                              void* d_out, int out_size) {
    const float* inp   = (const float*)d_in[0];
    const float* probs = (const float*)d_in[1];
    const float* ln1w  = (const float*)d_in[2];
    const float* ln1b  = (const float*)d_in[3];
    const float* ln2w  = (const float*)d_in[4];
    const float* ln2b  = (const float*)d_in[5];
    const float* w1    = (const float*)d_in[6];
    const float* b1    = (const float*)d_in[7];
    const float* la1   = (const float*)d_in[8];
    const float* lb1   = (const float*)d_in[9];
    const float* w2    = (const float*)d_in[10];
    const float* b2    = (const float*)d_in[11];
    const float* la2   = (const float*)d_in[12];
    const float* lb2   = (const float*)d_in[13];
    const float* wsca  = (const float*)d_in[14];
    const float* bsca  = (const float*)d_in[15];
    const float* lasca = (const float*)d_in[16];
    const float* lbsca = (const float*)d_in[17];
    const float* w3    = (const float*)d_in[18];
    const float* b3    = (const float*)d_in[19];
    const float* la3   = (const float*)d_in[20];
    const float* lb3   = (const float*)d_in[21];
    const float* w4    = (const float*)d_in[22];
    const float* b4    = (const float*)d_in[23];
    const float* la4   = (const float*)d_in[24];
    const float* lb4   = (const float*)d_in[25];
    const float* w5    = (const float*)d_in[26];
    const float* b5    = (const float*)d_in[27];
    const float* la5   = (const float*)d_in[28];
    const float* lb5   = (const float*)d_in[29];
    const float* beta  = (const float*)d_in[30];
    const float* gamma = (const float*)d_in[31];
    float* out = (float*)d_out;

    const int SM1 = (64 * XS1 + 128 * WS) * (int)sizeof(float);               // 68,608
    const int SM4 = ((64 + 128) * WS + 3 * 64 * PS4) * (int)sizeof(float);    // 104,448
    cudaFuncSetAttribute(k1_kernel, cudaFuncAttributeMaxDynamicSharedMemorySize, SM1);
    cudaFuncSetAttribute(k4_kernel, cudaFuncAttributeMaxDynamicSharedMemorySize, SM4);

    k_weights<<<dim3(6, Bn), 256>>>(probs,
                                    w1, la1, lb1, w2, la2, lb2,
                                    wsca, lasca, lbsca, w3, la3, lb3,
                                    w4, la4, lb4, w5, la5, lb5);
    k1_kernel<<<dim3(HWp / 128, Bn), 256, SM1>>>(inp, ln1w, ln1b, b1);
    k2_kernel<<<dim3(Hh / 4, Cc, Bn), 256>>>(b2);
    k4_kernel<<<dim3(HWp / 64, Bn), 256, SM4>>>(inp, ln2w, ln2b, bsca, b3, b4, b5, beta, gamma, out);
}

// round 11
// speedup vs baseline: 1.1083x; 1.0517x over previous
#include <cuda_runtime.h>

// ---------------- problem constants ----------------
#define Bn   4
#define Cc   64
#define DWc  128
#define Hh   256
#define Ww   256
#define HWp  65536            // H*W
#define EPSv 1e-6f
#define SCAL 2.0f

typedef unsigned long long u64;

// ---------------- packed f32x2 helpers (sm_103a FFMA2 path) ----------------
__device__ __forceinline__ u64 splat2(float w) {
    u64 r; unsigned int wi = __float_as_uint(w);
    asm("mov.b64 %0, {%1, %1};" : "=l"(r) : "r"(wi));
    return r;
}
__device__ __forceinline__ void ffma2(u64& d, u64 a, u64 b) {
    asm("fma.rn.f32x2 %0, %1, %2, %0;" : "+l"(d) : "l"(a), "l"(b));
}
__device__ __forceinline__ u64 add2(u64 a, u64 b) {
    u64 r; asm("add.rn.f32x2 %0, %1, %2;" : "=l"(r) : "l"(a), "l"(b)); return r;
}
__device__ __forceinline__ u64 mul2(u64 a, u64 b) {
    u64 r; asm("mul.rn.f32x2 %0, %1, %2;" : "=l"(r) : "l"(a), "l"(b)); return r;
}
__device__ __forceinline__ float2 unpack2(u64 v) {
    unsigned lo, hi;
    asm("mov.b64 {%0, %1}, %2;" : "=r"(lo), "=r"(hi) : "l"(v));
    float2 f; f.x = __uint_as_float(lo); f.y = __uint_as_float(hi);
    return f;
}

// ---------------- device scratch (no cudaMalloc allowed) ----------------
__device__ float g_w1  [Bn * DWc * Cc];
__device__ float g_w2  [Bn * DWc * 9];
__device__ float g_wsca[Bn * Cc * Cc];
__device__ float g_w3  [Bn * Cc * Cc];
__device__ float g_w4  [Bn * DWc * Cc];
__device__ float g_w5  [Bn * Cc * Cc];
__device__ float g_t1  [Bn * DWc * HWp];    // conv1 out
__device__ float g_xg  [Bn * Cc  * HWp];    // after simple_gate
__device__ float g_part[Bn * Cc * 64];      // deterministic pool partials

// ---------------- K0: gate + effective weights ----------------
__device__ __forceinline__ void mix1x1(const float* w, const float* la, const float* lb,
                                       float* dst, int O, int e, float gs, int t) {
    const float* lae = la + e * 4 * 64;
    int N = O * 64;
    for (int idx = t; idx < N; idx += 256) {
        int o = idx >> 6, i = idx & 63;
        const float* lbo = lb + (e * O + o) * 4;
        dst[idx] = w[idx] + gs * (lbo[0] * lae[i] + lbo[1] * lae[64 + i] +
                                  lbo[2] * lae[128 + i] + lbo[3] * lae[192 + i]);
    }
}

__global__ void k_weights(const float* __restrict__ probs,
                          const float* w1, const float* la1, const float* lb1,
                          const float* w2, const float* la2, const float* lb2,
                          const float* wsca, const float* lasca, const float* lbsca,
                          const float* w3, const float* la3, const float* lb3,
                          const float* w4, const float* la4, const float* lb4,
                          const float* w5, const float* la5, const float* lb5) {
    int b = blockIdx.y, job = blockIdx.x, t = threadIdx.x;
    float p0 = probs[b * 3 + 0], p1 = probs[b * 3 + 1], p2 = probs[b * 3 + 2];
    int e = 0; float g = p0;
    if (p1 > g) { g = p1; e = 1; }
    if (p2 > g) { g = p2; e = 2; }
    float gs = g * SCAL;

    if (job == 0) {
        mix1x1(w1, la1, lb1, g_w1 + b * DWc * Cc, DWc, e, gs, t);
    } else if (job == 1) {
        for (int idx = t; idx < DWc * 9; idx += 256) {
            int row = idx / 3, col = idx - row * 3;
            const float* lbo = lb2 + (e * 384 + row) * 12;
            const float* lae = la2 + e * 36 + col;
            float acc = w2[idx];
            #pragma unroll
            for (int r = 0; r < 12; ++r) acc += gs * lbo[r] * lae[r * 3];
            g_w2[b * DWc * 9 + idx] = acc;
        }
    } else if (job == 2) {
        mix1x1(wsca, lasca, lbsca, g_wsca + b * Cc * Cc, Cc, e, gs, t);
    } else if (job == 3) {
        mix1x1(w3, la3, lb3, g_w3 + b * Cc * Cc, Cc, e, gs, t);
    } else if (job == 4) {
        mix1x1(w4, la4, lb4, g_w4 + b * DWc * Cc, DWc, e, gs, t);
    } else {
        mix1x1(w5, la5, lb5, g_w5 + b * Cc * Cc, Cc, e, gs, t);
    }
}

// ---------------- K1: LN1 + conv1 (1x1, 64->128) ----------------
// grid (1024, B), block 256.  Tile = 64 px.  Thread: 8 oc x 4 px.
// Weights straight from gmem (L1-cached broadcast float4), x in smem stride 68.
#define XS 68
__global__ void __launch_bounds__(256, 3)
k1_kernel(const float* __restrict__ inp,
          const float* __restrict__ ln1w, const float* __restrict__ ln1b,
          const float* __restrict__ b1) {
    __shared__ float xs[64 * XS];
    __shared__ float sred[256], qred[256], smean[64], sinv[64];
    __shared__ float lnws[64], lnbs[64];

    int b = blockIdx.y;
    int pix0 = blockIdx.x * 64;
    int t = threadIdx.x;

    if (t < 64) { lnws[t] = ln1w[t]; lnbs[t] = ln1b[t]; }

    const float* ib = inp + b * Cc * HWp + pix0;
    #pragma unroll
    for (int it = 0; it < 16; ++it) {
        int idx = it * 256 + t;
        int c = idx >> 6, p = idx & 63;
        xs[c * XS + p] = ib[c * HWp + p];
    }
    __syncthreads();

    // LN1 (conflict-free): thread -> pixel p = t&63, quarter qq = t>>6 (16 channels)
    {
        int p = t & 63, qq = t >> 6;
        float s = 0.f, qs = 0.f;
        #pragma unroll
        for (int c = 0; c < 16; ++c) {
            float v = xs[(qq * 16 + c) * XS + p];
            s += v; qs += v * v;
        }
        sred[t] = s; qred[t] = qs;
        __syncthreads();
        if (t < 64) {
            float S = sred[t] + sred[t + 64] + sred[t + 128] + sred[t + 192];
            float Q = qred[t] + qred[t + 64] + qred[t + 128] + qred[t + 192];
            float mean = S * (1.f / 64.f);
            float var  = Q * (1.f / 64.f) - mean * mean;
            smean[t] = mean;
            sinv[t]  = rsqrtf(var + EPSv);
        }
        __syncthreads();
        float mean = smean[p], inv = sinv[p];
        #pragma unroll
        for (int c = 0; c < 16; ++c) {
            int ch = qq * 16 + c;
            float v = xs[ch * XS + p];
            xs[ch * XS + p] = (v - mean) * inv * lnws[ch] + lnbs[ch];
        }
    }
    __syncthreads();

    // GEMM: 128 oc x 64 px, K=64.  Thread: 8 oc x 4 px.  Weights via __ldg float4.
    int oc0 = (t >> 4) * 8, px0 = (t & 15) * 4;
    const float* wb = g_w1 + b * DWc * Cc;
    u64 acc[8][2];
    #pragma unroll
    for (int u = 0; u < 8; ++u) { acc[u][0] = 0ull; acc[u][1] = 0ull; }

    for (int kc = 0; kc < 64; kc += 4) {
        ulonglong2 x0 = *(const ulonglong2*)(xs + (kc + 0) * XS + px0);
        ulonglong2 x1 = *(const ulonglong2*)(xs + (kc + 1) * XS + px0);
        ulonglong2 x2 = *(const ulonglong2*)(xs + (kc + 2) * XS + px0);
        ulonglong2 x3 = *(const ulonglong2*)(xs + (kc + 3) * XS + px0);
        #pragma unroll
        for (int u = 0; u < 8; ++u) {
            float4 wv = __ldg((const float4*)(wb + (oc0 + u) * Cc + kc));
            u64 w0 = splat2(wv.x), w1s = splat2(wv.y);
            u64 w2s = splat2(wv.z), w3s = splat2(wv.w);
            ffma2(acc[u][0], w0, x0.x);  ffma2(acc[u][1], w0, x0.y);
            ffma2(acc[u][0], w1s, x1.x); ffma2(acc[u][1], w1s, x1.y);
            ffma2(acc[u][0], w2s, x2.x); ffma2(acc[u][1], w2s, x2.y);
            ffma2(acc[u][0], w3s, x3.x); ffma2(acc[u][1], w3s, x3.y);
        }
    }

    float* ob = g_t1 + b * DWc * HWp + pix0 + px0;
    #pragma unroll
    for (int u = 0; u < 8; ++u) {
        float bias = __ldg(&b1[oc0 + u]);
        float2 p0 = unpack2(acc[u][0]), p1 = unpack2(acc[u][1]);
        float4 r = make_float4(p0.x + bias, p0.y + bias, p1.x + bias, p1.y + bias);
        *(float4*)(ob + (oc0 + u) * HWp) = r;
    }
}

// ---------------- K2: depthwise 3x3 + simple_gate + pool partials ----------------
__global__ void k2_kernel(const float* __restrict__ b2) {
    __shared__ float s0[6][256];
    __shared__ float s1[6][256];
    __shared__ float red[256];

    int b = blockIdx.z, c = blockIdx.y;
    int r0 = blockIdx.x * 4;
    int t = threadIdx.x;

    const float* t1a = g_t1 + (b * DWc + c) * HWp;
    const float* t1b = g_t1 + (b * DWc + c + 64) * HWp;

    #pragma unroll
    for (int lr = 0; lr < 6; ++lr) {
        int gr = r0 + lr - 1;
        bool ok = (gr >= 0 && gr < Hh);
        s0[lr][t] = ok ? t1a[gr * Ww + t] : 0.f;
        s1[lr][t] = ok ? t1b[gr * Ww + t] : 0.f;
    }
    __syncthreads();

    float wa[9], wb9[9];
    const float* w2a = g_w2 + (b * DWc + c) * 9;
    const float* w2b = g_w2 + (b * DWc + c + 64) * 9;
    #pragma unroll
    for (int i = 0; i < 9; ++i) { wa[i] = __ldg(&w2a[i]); wb9[i] = __ldg(&w2b[i]); }
    float biasA = __ldg(&b2[c]), biasB = __ldg(&b2[c + 64]);

    float* xgp = g_xg + (b * Cc + c) * HWp;
    float lsum = 0.f;
    int w = t;
    #pragma unroll
    for (int j = 0; j < 4; ++j) {
        float a0 = biasA, a1 = biasB;
        #pragma unroll
        for (int kh = 0; kh < 3; ++kh) {
            #pragma unroll
            for (int kw = 0; kw < 3; ++kw) {
                int col = w + kw - 1;
                bool ok = (col >= 0 && col < Ww);
                float v0 = ok ? s0[j + kh][col] : 0.f;
                float v1 = ok ? s1[j + kh][col] : 0.f;
                a0 += wa[kh * 3 + kw] * v0;
                a1 += wb9[kh * 3 + kw] * v1;
            }
        }
        float val = a0 * a1;
        xgp[(r0 + j) * Ww + w] = val;
        lsum += val;
    }

    red[t] = lsum;
    __syncthreads();
    #pragma unroll
    for (int o = 128; o > 0; o >>= 1) {
        if (t < o) red[t] += red[t + o];
        __syncthreads();
    }
    if (t == 0) g_part[(b * Cc + c) * 64 + blockIdx.x] = red[0];
}

// ---------------- K4: fused per-pixel tail ----------------
// grid (1024, B), block 256.  Tile = 64 px.  Pixel buffers only in smem (stride 68);
// all weights loaded straight from gmem (L1-cached broadcast float4).
#define PS4 68
__global__ void __launch_bounds__(256, 3)
k4_kernel(const float* __restrict__ inp,
          const float* __restrict__ ln2w, const float* __restrict__ ln2b,
          const float* __restrict__ bsca,
          const float* __restrict__ b3, const float* __restrict__ b4,
          const float* __restrict__ b5,
          const float* __restrict__ beta, const float* __restrict__ gamma,
          float* __restrict__ out) {
    extern __shared__ float sm[];
    float* xsb = sm;                   // 64*68 (x, then LN2 output)
    float* ysb = xsb + 64 * PS4;       // 64*68 (residual y)
    float* gsb = ysb + 64 * PS4;       // 64*68 (gate output)
    __shared__ float sred[256], qred[256], smean[64], sinv[64];
    __shared__ float lnws[64], lnbs[64];
    __shared__ float s_pool[64], s_sca[64];

    int b = blockIdx.y;
    int pix0 = blockIdx.x * 64;
    int t = threadIdx.x;

    if (t < 64) { lnws[t] = ln2w[t]; lnbs[t] = ln2b[t]; }
    // pool mean from partials (k3 fold)
    if (t < 64) {
        float s = 0.f;
        const float4* pp = (const float4*)(g_part + (b * Cc + t) * 64);
        #pragma unroll
        for (int k = 0; k < 16; ++k) {
            float4 v = pp[k];
            s += (v.x + v.y) + (v.z + v.w);
        }
        s_pool[t] = s * (1.f / (float)HWp);
    }
    __syncthreads();
    if (t < 64) {
        const float* wr = g_wsca + b * Cc * Cc + t * Cc;
        float acc = __ldg(&bsca[t]);
        #pragma unroll
        for (int i = 0; i < 64; ++i) acc += wr[i] * s_pool[i];
        s_sca[t] = acc;
    }
    __syncthreads();

    const float* xgb = g_xg + b * Cc * HWp + pix0;
    const float* ib  = inp  + b * Cc * HWp + pix0;
    #pragma unroll
    for (int it = 0; it < 16; ++it) {
        int idx = it * 256 + t;
        int c = idx >> 6, p = idx & 63;
        float sc = s_sca[c];
        xsb[c * PS4 + p] = xgb[c * HWp + p] * sc;
        ysb[c * PS4 + p] = ib[c * HWp + p];
    }
    __syncthreads();

    int tg = t >> 4, px0 = (t & 15) * 4;
    const float* wb3 = g_w3 + b * Cc * Cc;
    const float* wb4 = g_w4 + b * DWc * Cc;
    const float* wb5 = g_w5 + b * Cc * Cc;

    // matvec1: conv3 (64x64); thread 4 oc x 4 px.  y = inp + (t3+bias)*beta
    {
        int oc0 = tg * 4;
        u64 a1[4][2];
        #pragma unroll
        for (int u = 0; u < 4; ++u) { a1[u][0] = 0ull; a1[u][1] = 0ull; }
        for (int kc = 0; kc < 64; kc += 4) {
            ulonglong2 x0 = *(const ulonglong2*)(xsb + (kc + 0) * PS4 + px0);
            ulonglong2 x1 = *(const ulonglong2*)(xsb + (kc + 1) * PS4 + px0);
            ulonglong2 x2 = *(const ulonglong2*)(xsb + (kc + 2) * PS4 + px0);
            ulonglong2 x3 = *(const ulonglong2*)(xsb + (kc + 3) * PS4 + px0);
            #pragma unroll
            for (int u = 0; u < 4; ++u) {
                float4 wv = __ldg((const float4*)(wb3 + (oc0 + u) * Cc + kc));
                u64 w0 = splat2(wv.x), w1s = splat2(wv.y);
                u64 w2s = splat2(wv.z), w3s = splat2(wv.w);
                ffma2(a1[u][0], w0, x0.x);  ffma2(a1[u][1], w0, x0.y);
                ffma2(a1[u][0], w1s, x1.x); ffma2(a1[u][1], w1s, x1.y);
                ffma2(a1[u][0], w2s, x2.x); ffma2(a1[u][1], w2s, x2.y);
                ffma2(a1[u][0], w3s, x3.x); ffma2(a1[u][1], w3s, x3.y);
            }
        }
        #pragma unroll
        for (int u = 0; u < 4; ++u) {
            int o = oc0 + u;
            float bt = __ldg(&beta[o]);
            float bias = __ldg(&b3[o]);
            float2 p0 = unpack2(a1[u][0]), p1 = unpack2(a1[u][1]);
            float4* yv = (float4*)(ysb + o * PS4 + px0);
            float4 y = *yv;
            y.x += (p0.x + bias) * bt;
            y.y += (p0.y + bias) * bt;
            y.z += (p1.x + bias) * bt;
            y.w += (p1.y + bias) * bt;
            *yv = y;
        }
    }
    __syncthreads();

    // LN2 (conflict-free): thread -> pixel p = t&63, quarter qq = t>>6.
    // Output -> xsb (dead after matvec1).
    {
        int p = t & 63, qq = t >> 6;
        float s = 0.f, qs = 0.f;
        #pragma unroll
        for (int c = 0; c < 16; ++c) {
            float v = ysb[(qq * 16 + c) * PS4 + p];
            s += v; qs += v * v;
        }
        sred[t] = s; qred[t] = qs;
        __syncthreads();
        if (t < 64) {
            float S = sred[t] + sred[t + 64] + sred[t + 128] + sred[t + 192];
            float Q = qred[t] + qred[t + 64] + qred[t + 128] + qred[t + 192];
            float mean = S * (1.f / 64.f);
            float var  = Q * (1.f / 64.f) - mean * mean;
            smean[t] = mean;
            sinv[t]  = rsqrtf(var + EPSv);
        }
        __syncthreads();
        float mean = smean[p], inv = sinv[p];
        #pragma unroll
        for (int c = 0; c < 16; ++c) {
            int ch = qq * 16 + c;
            float v = ysb[ch * PS4 + p];
            xsb[ch * PS4 + p] = (v - mean) * inv * lnws[ch] + lnbs[ch];
        }
    }
    __syncthreads();

    // matvec2: conv4 (128x64) + simple_gate. oc = tg + 16*j keeps gate pairs in-thread.
    {
        u64 a2[8][2];
        #pragma unroll
        for (int j = 0; j < 8; ++j) { a2[j][0] = 0ull; a2[j][1] = 0ull; }
        for (int kc = 0; kc < 64; kc += 4) {
            ulonglong2 z0 = *(const ulonglong2*)(xsb + (kc + 0) * PS4 + px0);
            ulonglong2 z1 = *(const ulonglong2*)(xsb + (kc + 1) * PS4 + px0);
            ulonglong2 z2 = *(const ulonglong2*)(xsb + (kc + 2) * PS4 + px0);
            ulonglong2 z3 = *(const ulonglong2*)(xsb + (kc + 3) * PS4 + px0);
            #pragma unroll
            for (int j = 0; j < 8; ++j) {
                float4 wv = __ldg((const float4*)(wb4 + (tg + 16 * j) * Cc + kc));
                u64 w0 = splat2(wv.x), w1s = splat2(wv.y);
                u64 w2s = splat2(wv.z), w3s = splat2(wv.w);
                ffma2(a2[j][0], w0, z0.x);  ffma2(a2[j][1], w0, z0.y);
                ffma2(a2[j][0], w1s, z1.x); ffma2(a2[j][1], w1s, z1.y);
                ffma2(a2[j][0], w2s, z2.x); ffma2(a2[j][1], w2s, z2.y);
                ffma2(a2[j][0], w3s, z3.x); ffma2(a2[j][1], w3s, z3.y);
            }
        }
        #pragma unroll
        for (int j = 0; j < 4; ++j) {
            int o = tg + 16 * j;
            u64 bl = splat2(__ldg(&b4[o]));
            u64 bh = splat2(__ldg(&b4[o + 64]));
            ulonglong2 gv;
            gv.x = mul2(add2(a2[j][0], bl), add2(a2[j + 4][0], bh));
            gv.y = mul2(add2(a2[j][1], bl), add2(a2[j + 4][1], bh));
            *(ulonglong2*)(gsb + o * PS4 + px0) = gv;
        }
    }
    __syncthreads();

    // matvec3: conv5 (64x64);  out = y + (t5+bias)*gamma
    {
        int oc0 = tg * 4;
        u64 a3[4][2];
        #pragma unroll
        for (int u = 0; u < 4; ++u) { a3[u][0] = 0ull; a3[u][1] = 0ull; }
        for (int kc = 0; kc < 64; kc += 4) {
            ulonglong2 g0 = *(const ulonglong2*)(gsb + (kc + 0) * PS4 + px0);
            ulonglong2 g1 = *(const ulonglong2*)(gsb + (kc + 1) * PS4 + px0);
            ulonglong2 g2 = *(const ulonglong2*)(gsb + (kc + 2) * PS4 + px0);
            ulonglong2 g3 = *(const ulonglong2*)(gsb + (kc + 3) * PS4 + px0);
            #pragma unroll
            for (int u = 0; u < 4; ++u) {
                float4 wv = __ldg((const float4*)(wb5 + (oc0 + u) * Cc + kc));
                u64 w0 = splat2(wv.x), w1s = splat2(wv.y);
                u64 w2s = splat2(wv.z), w3s = splat2(wv.w);
                ffma2(a3[u][0], w0, g0.x);  ffma2(a3[u][1], w0, g0.y);
                ffma2(a3[u][0], w1s, g1.x); ffma2(a3[u][1], w1s, g1.y);
                ffma2(a3[u][0], w2s, g2.x); ffma2(a3[u][1], w2s, g2.y);
                ffma2(a3[u][0], w3s, g3.x); ffma2(a3[u][1], w3s, g3.y);
            }
        }
        float* ob = out + b * Cc * HWp + pix0 + px0;
        #pragma unroll
        for (int u = 0; u < 4; ++u) {
            int o = oc0 + u;
            float gm = __ldg(&gamma[o]);
            float bias = __ldg(&b5[o]);
            float2 p0 = unpack2(a3[u][0]), p1 = unpack2(a3[u][1]);
            float4 yv = *(const float4*)(ysb + o * PS4 + px0);
            float4 r;
            r.x = yv.x + (p0.x + bias) * gm;
            r.y = yv.y + (p0.y + bias) * gm;
            r.z = yv.z + (p1.x + bias) * gm;
            r.w = yv.w + (p1.y + bias) * gm;
            *(float4*)(ob + o * HWp) = r;
        }
    }
}

// ---------------- launch ----------------
extern "C" void kernel_launch(void* const* d_in, const int* in_sizes, int n_in,
                              void* d_out, int out_size) {
    const float* inp   = (const float*)d_in[0];
    const float* probs = (const float*)d_in[1];
    const float* ln1w  = (const float*)d_in[2];
    const float* ln1b  = (const float*)d_in[3];
    const float* ln2w  = (const float*)d_in[4];
    const float* ln2b  = (const float*)d_in[5];
    const float* w1    = (const float*)d_in[6];
    const float* b1    = (const float*)d_in[7];
    const float* la1   = (const float*)d_in[8];
    const float* lb1   = (const float*)d_in[9];
    const float* w2    = (const float*)d_in[10];
    const float* b2    = (const float*)d_in[11];
    const float* la2   = (const float*)d_in[12];
    const float* lb2   = (const float*)d_in[13];
    const float* wsca  = (const float*)d_in[14];
    const float* bsca  = (const float*)d_in[15];
    const float* lasca = (const float*)d_in[16];
    const float* lbsca = (const float*)d_in[17];
    const float* w3    = (const float*)d_in[18];
    const float* b3    = (const float*)d_in[19];
    const float* la3   = (const float*)d_in[20];
    const float* lb3   = (const float*)d_in[21];
    const float* w4    = (const float*)d_in[22];
    const float* b4    = (const float*)d_in[23];
    const float* la4   = (const float*)d_in[24];
    const float* lb4   = (const float*)d_in[25];
    const float* w5    = (const float*)d_in[26];
    const float* b5    = (const float*)d_in[27];
    const float* la5   = (const float*)d_in[28];
    const float* lb5   = (const float*)d_in[29];
    const float* beta  = (const float*)d_in[30];
    const float* gamma = (const float*)d_in[31];
    float* out = (float*)d_out;

    const int SM4 = (3 * 64 * PS4) * (int)sizeof(float);   // 52,224
    cudaFuncSetAttribute(k4_kernel, cudaFuncAttributeMaxDynamicSharedMemorySize, SM4);

    k_weights<<<dim3(6, Bn), 256>>>(probs,
                                    w1, la1, lb1, w2, la2, lb2,
                                    wsca, lasca, lbsca, w3, la3, lb3,
                                    w4, la4, lb4, w5, la5, lb5);
    k1_kernel<<<dim3(HWp / 64, Bn), 256>>>(inp, ln1w, ln1b, b1);
    k2_kernel<<<dim3(Hh / 4, Cc, Bn), 256>>>(b2);
    k4_kernel<<<dim3(HWp / 64, Bn), 256, SM4>>>(inp, ln2w, ln2b, bsca, b3, b4, b5, beta, gamma, out);
}

// round 13
// speedup vs baseline: 1.3096x; 1.1816x over previous
#include <cuda_runtime.h>

// ---------------- problem constants ----------------
#define Bn   4
#define Cc   64
#define DWc  128
#define Hh   256
#define Ww   256
#define HWp  65536            // H*W
#define EPSv 1e-6f
#define SCAL 2.0f

typedef unsigned long long u64;

// ---------------- packed f32x2 helpers (sm_103a FFMA2 path) ----------------
__device__ __forceinline__ u64 splat2(float w) {
    u64 r; unsigned int wi = __float_as_uint(w);
    asm("mov.b64 %0, {%1, %1};" : "=l"(r) : "r"(wi));
    return r;
}
__device__ __forceinline__ void ffma2(u64& d, u64 a, u64 b) {
    asm("fma.rn.f32x2 %0, %1, %2, %0;" : "+l"(d) : "l"(a), "l"(b));
}
__device__ __forceinline__ u64 add2(u64 a, u64 b) {
    u64 r; asm("add.rn.f32x2 %0, %1, %2;" : "=l"(r) : "l"(a), "l"(b)); return r;
}
__device__ __forceinline__ u64 mul2(u64 a, u64 b) {
    u64 r; asm("mul.rn.f32x2 %0, %1, %2;" : "=l"(r) : "l"(a), "l"(b)); return r;
}
__device__ __forceinline__ float2 unpack2(u64 v) {
    unsigned lo, hi;
    asm("mov.b64 {%0, %1}, %2;" : "=r"(lo), "=r"(hi) : "l"(v));
    float2 f; f.x = __uint_as_float(lo); f.y = __uint_as_float(hi);
    return f;
}

// ---------------- device scratch (no cudaMalloc allowed) ----------------
__device__ float g_w1  [Bn * DWc * Cc];
__device__ float g_w2  [Bn * DWc * 9];
__device__ float g_wsca[Bn * Cc * Cc];
__device__ float g_w3  [Bn * Cc * Cc];
__device__ float g_w4  [Bn * DWc * Cc];
__device__ float g_w5  [Bn * Cc * Cc];
__device__ float g_t1  [Bn * DWc * HWp];    // conv1 out
__device__ float g_xg  [Bn * Cc  * HWp];    // after simple_gate
__device__ float g_part[Bn * Cc * 64];      // deterministic pool partials

// ---------------- K0: gate + effective weights ----------------
__device__ __forceinline__ void mix1x1(const float* w, const float* la, const float* lb,
                                       float* dst, int O, int e, float gs, int t) {
    const float* lae = la + e * 4 * 64;
    int N = O * 64;
    for (int idx = t; idx < N; idx += 256) {
        int o = idx >> 6, i = idx & 63;
        const float* lbo = lb + (e * O + o) * 4;
        dst[idx] = w[idx] + gs * (lbo[0] * lae[i] + lbo[1] * lae[64 + i] +
                                  lbo[2] * lae[128 + i] + lbo[3] * lae[192 + i]);
    }
}

__global__ void k_weights(const float* __restrict__ probs,
                          const float* w1, const float* la1, const float* lb1,
                          const float* w2, const float* la2, const float* lb2,
                          const float* wsca, const float* lasca, const float* lbsca,
                          const float* w3, const float* la3, const float* lb3,
                          const float* w4, const float* la4, const float* lb4,
                          const float* w5, const float* la5, const float* lb5) {
    int b = blockIdx.y, job = blockIdx.x, t = threadIdx.x;
    float p0 = probs[b * 3 + 0], p1 = probs[b * 3 + 1], p2 = probs[b * 3 + 2];
    int e = 0; float g = p0;
    if (p1 > g) { g = p1; e = 1; }
    if (p2 > g) { g = p2; e = 2; }
    float gs = g * SCAL;

    if (job == 0) {
        mix1x1(w1, la1, lb1, g_w1 + b * DWc * Cc, DWc, e, gs, t);
    } else if (job == 1) {
        for (int idx = t; idx < DWc * 9; idx += 256) {
            int row = idx / 3, col = idx - row * 3;
            const float* lbo = lb2 + (e * 384 + row) * 12;
            const float* lae = la2 + e * 36 + col;
            float acc = w2[idx];
            #pragma unroll
            for (int r = 0; r < 12; ++r) acc += gs * lbo[r] * lae[r * 3];
            g_w2[b * DWc * 9 + idx] = acc;
        }
    } else if (job == 2) {
        mix1x1(wsca, lasca, lbsca, g_wsca + b * Cc * Cc, Cc, e, gs, t);
    } else if (job == 3) {
        mix1x1(w3, la3, lb3, g_w3 + b * Cc * Cc, Cc, e, gs, t);
    } else if (job == 4) {
        mix1x1(w4, la4, lb4, g_w4 + b * DWc * Cc, DWc, e, gs, t);
    } else {
        mix1x1(w5, la5, lb5, g_w5 + b * Cc * Cc, Cc, e, gs, t);
    }
}

// ---------------- K1: LN1 + conv1 (1x1, 64->128) ----------------
// grid (512, B), block 256.  Tile = 128 px.  Thread: 8 oc x 8 px ({px0..+3, px0+64..+67}).
// Weights straight from gmem (L1-cached broadcast float4); x in smem stride 132.
#define XS1 132
__global__ void __launch_bounds__(256, 2)
k1_kernel(const float* __restrict__ inp,
          const float* __restrict__ ln1w, const float* __restrict__ ln1b,
          const float* __restrict__ b1) {
    __shared__ float xs[64 * XS1];
    __shared__ float sred[256], qred[256], smean[128], sinv[128];
    __shared__ float lnws[64], lnbs[64];

    int b = blockIdx.y;
    int pix0 = blockIdx.x * 128;
    int t = threadIdx.x;

    if (t < 64) { lnws[t] = ln1w[t]; lnbs[t] = ln1b[t]; }

    const float* ib = inp + b * Cc * HWp + pix0;
    #pragma unroll
    for (int it = 0; it < 32; ++it) {
        int idx = it * 256 + t;
        int c = idx >> 7, p = idx & 127;
        xs[c * XS1 + p] = ib[c * HWp + p];
    }
    __syncthreads();

    // LN1 (conflict-free): thread -> pixel p = t&127, half hh = t>>7 (32 channels)
    {
        int p = t & 127, hh = t >> 7;
        float s = 0.f, qs = 0.f;
        #pragma unroll
        for (int c = 0; c < 32; ++c) {
            float v = xs[(hh * 32 + c) * XS1 + p];
            s += v; qs += v * v;
        }
        sred[t] = s; qred[t] = qs;
        __syncthreads();
        if (t < 128) {
            float S = sred[t] + sred[t + 128];
            float Q = qred[t] + qred[t + 128];
            float mean = S * (1.f / 64.f);
            float var  = Q * (1.f / 64.f) - mean * mean;
            smean[t] = mean;
            sinv[t]  = rsqrtf(var + EPSv);
        }
        __syncthreads();
        float mean = smean[p], inv = sinv[p];
        #pragma unroll
        for (int c = 0; c < 32; ++c) {
            int ch = hh * 32 + c;
            float v = xs[ch * XS1 + p];
            xs[ch * XS1 + p] = (v - mean) * inv * lnws[ch] + lnbs[ch];
        }
    }
    __syncthreads();

    // GEMM: 128 oc x 128 px, K=64.  Thread: 8 oc x 8 px.  Weights via __ldg float4.
    int oc0 = (t >> 4) * 8, px0 = (t & 15) * 4;
    const float* wb = g_w1 + b * DWc * Cc;
    u64 acc[8][4];
    #pragma unroll
    for (int u = 0; u < 8; ++u)
        #pragma unroll
        for (int v = 0; v < 4; ++v) acc[u][v] = 0ull;

    for (int kc = 0; kc < 64; kc += 4) {
        ulonglong2 xA0 = *(const ulonglong2*)(xs + (kc + 0) * XS1 + px0);
        ulonglong2 xB0 = *(const ulonglong2*)(xs + (kc + 0) * XS1 + px0 + 64);
        ulonglong2 xA1 = *(const ulonglong2*)(xs + (kc + 1) * XS1 + px0);
        ulonglong2 xB1 = *(const ulonglong2*)(xs + (kc + 1) * XS1 + px0 + 64);
        ulonglong2 xA2 = *(const ulonglong2*)(xs + (kc + 2) * XS1 + px0);
        ulonglong2 xB2 = *(const ulonglong2*)(xs + (kc + 2) * XS1 + px0 + 64);
        ulonglong2 xA3 = *(const ulonglong2*)(xs + (kc + 3) * XS1 + px0);
        ulonglong2 xB3 = *(const ulonglong2*)(xs + (kc + 3) * XS1 + px0 + 64);
        #pragma unroll
        for (int u = 0; u < 8; ++u) {
            float4 wv = __ldg((const float4*)(wb + (oc0 + u) * Cc + kc));
            u64 w0 = splat2(wv.x), w1s = splat2(wv.y);
            u64 w2s = splat2(wv.z), w3s = splat2(wv.w);
            ffma2(acc[u][0], w0, xA0.x);  ffma2(acc[u][1], w0, xA0.y);
            ffma2(acc[u][2], w0, xB0.x);  ffma2(acc[u][3], w0, xB0.y);
            ffma2(acc[u][0], w1s, xA1.x); ffma2(acc[u][1], w1s, xA1.y);
            ffma2(acc[u][2], w1s, xB1.x); ffma2(acc[u][3], w1s, xB1.y);
            ffma2(acc[u][0], w2s, xA2.x); ffma2(acc[u][1], w2s, xA2.y);
            ffma2(acc[u][2], w2s, xB2.x); ffma2(acc[u][3], w2s, xB2.y);
            ffma2(acc[u][0], w3s, xA3.x); ffma2(acc[u][1], w3s, xA3.y);
            ffma2(acc[u][2], w3s, xB3.x); ffma2(acc[u][3], w3s, xB3.y);
        }
    }

    float* ob = g_t1 + b * DWc * HWp + pix0 + px0;
    #pragma unroll
    for (int u = 0; u < 8; ++u) {
        float bias = __ldg(&b1[oc0 + u]);
        float2 p0 = unpack2(acc[u][0]), p1 = unpack2(acc[u][1]);
        float2 p2 = unpack2(acc[u][2]), p3 = unpack2(acc[u][3]);
        float4 r0 = make_float4(p0.x + bias, p0.y + bias, p1.x + bias, p1.y + bias);
        float4 r1 = make_float4(p2.x + bias, p2.y + bias, p3.x + bias, p3.y + bias);
        *(float4*)(ob + (oc0 + u) * HWp)      = r0;
        *(float4*)(ob + (oc0 + u) * HWp + 64) = r1;
    }
}

// ---------------- K2: depthwise 3x3 + simple_gate + pool partials ----------------
__global__ void k2_kernel(const float* __restrict__ b2) {
    __shared__ float s0[6][256];
    __shared__ float s1[6][256];
    __shared__ float red[256];

    int b = blockIdx.z, c = blockIdx.y;
    int r0 = blockIdx.x * 4;
    int t = threadIdx.x;

    const float* t1a = g_t1 + (b * DWc + c) * HWp;
    const float* t1b = g_t1 + (b * DWc + c + 64) * HWp;

    #pragma unroll
    for (int lr = 0; lr < 6; ++lr) {
        int gr = r0 + lr - 1;
        bool ok = (gr >= 0 && gr < Hh);
        s0[lr][t] = ok ? t1a[gr * Ww + t] : 0.f;
        s1[lr][t] = ok ? t1b[gr * Ww + t] : 0.f;
    }
    __syncthreads();

    float wa[9], wb9[9];
    const float* w2a = g_w2 + (b * DWc + c) * 9;
    const float* w2b = g_w2 + (b * DWc + c + 64) * 9;
    #pragma unroll
    for (int i = 0; i < 9; ++i) { wa[i] = __ldg(&w2a[i]); wb9[i] = __ldg(&w2b[i]); }
    float biasA = __ldg(&b2[c]), biasB = __ldg(&b2[c + 64]);

    float* xgp = g_xg + (b * Cc + c) * HWp;
    float lsum = 0.f;
    int w = t;
    #pragma unroll
    for (int j = 0; j < 4; ++j) {
        float a0 = biasA, a1 = biasB;
        #pragma unroll
        for (int kh = 0; kh < 3; ++kh) {
            #pragma unroll
            for (int kw = 0; kw < 3; ++kw) {
                int col = w + kw - 1;
                bool ok = (col >= 0 && col < Ww);
                float v0 = ok ? s0[j + kh][col] : 0.f;
                float v1 = ok ? s1[j + kh][col] : 0.f;
                a0 += wa[kh * 3 + kw] * v0;
                a1 += wb9[kh * 3 + kw] * v1;
            }
        }
        float val = a0 * a1;
        xgp[(r0 + j) * Ww + w] = val;
        lsum += val;
    }

    red[t] = lsum;
    __syncthreads();
    #pragma unroll
    for (int o = 128; o > 0; o >>= 1) {
        if (t < o) red[t] += red[t + o];
        __syncthreads();
    }
    if (t == 0) g_part[(b * Cc + c) * 64 + blockIdx.x] = red[0];
}

// ---------------- K4: fused per-pixel tail ----------------
// grid (512, B), block 256.  Tile = 128 px, thread = 8 px ({px0..+3, px0+64..+67}).
// Pixel buffers in dynamic smem (stride 132); weights via gmem L1-cached float4.
#define PS4 132
__global__ void __launch_bounds__(256, 2)
k4_kernel(const float* __restrict__ inp,
          const float* __restrict__ ln2w, const float* __restrict__ ln2b,
          const float* __restrict__ bsca,
          const float* __restrict__ b3, const float* __restrict__ b4,
          const float* __restrict__ b5,
          const float* __restrict__ beta, const float* __restrict__ gamma,
          float* __restrict__ out) {
    extern __shared__ float sm[];
    float* xsb = sm;                   // 64*132 (x, then LN2 output)
    float* ysb = xsb + 64 * PS4;       // 64*132 (residual y)
    float* gsb = ysb + 64 * PS4;       // 64*132 (gate output)
    __shared__ float sred[256], qred[256], smean[128], sinv[128];
    __shared__ float lnws[64], lnbs[64];
    __shared__ float s_pool[64], s_sca[64];

    int b = blockIdx.y;
    int pix0 = blockIdx.x * 128;
    int t = threadIdx.x;

    if (t < 64) { lnws[t] = ln2w[t]; lnbs[t] = ln2b[t]; }
    // pool mean from partials (k3 fold)
    if (t < 64) {
        float s = 0.f;
        const float4* pp = (const float4*)(g_part + (b * Cc + t) * 64);
        #pragma unroll
        for (int k = 0; k < 16; ++k) {
            float4 v = pp[k];
            s += (v.x + v.y) + (v.z + v.w);
        }
        s_pool[t] = s * (1.f / (float)HWp);
    }
    __syncthreads();
    if (t < 64) {
        const float* wr = g_wsca + b * Cc * Cc + t * Cc;
        float acc = __ldg(&bsca[t]);
        #pragma unroll
        for (int i = 0; i < 64; ++i) acc += wr[i] * s_pool[i];
        s_sca[t] = acc;
    }
    __syncthreads();

    const float* xgb = g_xg + b * Cc * HWp + pix0;
    const float* ib  = inp  + b * Cc * HWp + pix0;
    #pragma unroll
    for (int it = 0; it < 32; ++it) {
        int idx = it * 256 + t;
        int c = idx >> 7, p = idx & 127;
        float sc = s_sca[c];
        xsb[c * PS4 + p] = xgb[c * HWp + p] * sc;
        ysb[c * PS4 + p] = ib[c * HWp + p];
    }
    __syncthreads();

    int tg = t >> 4, px0 = (t & 15) * 4;
    const float* wb3 = g_w3 + b * Cc * Cc;
    const float* wb4 = g_w4 + b * DWc * Cc;
    const float* wb5 = g_w5 + b * Cc * Cc;

    // matvec1: conv3 (64x64); thread 4 oc x 8 px.  y = inp + (t3+bias)*beta
    {
        int oc0 = tg * 4;
        u64 a1[4][4];
        #pragma unroll
        for (int u = 0; u < 4; ++u)
            #pragma unroll
            for (int v = 0; v < 4; ++v) a1[u][v] = 0ull;
        for (int kc = 0; kc < 64; kc += 4) {
            ulonglong2 xA0 = *(const ulonglong2*)(xsb + (kc + 0) * PS4 + px0);
            ulonglong2 xB0 = *(const ulonglong2*)(xsb + (kc + 0) * PS4 + px0 + 64);
            ulonglong2 xA1 = *(const ulonglong2*)(xsb + (kc + 1) * PS4 + px0);
            ulonglong2 xB1 = *(const ulonglong2*)(xsb + (kc + 1) * PS4 + px0 + 64);
            ulonglong2 xA2 = *(const ulonglong2*)(xsb + (kc + 2) * PS4 + px0);
            ulonglong2 xB2 = *(const ulonglong2*)(xsb + (kc + 2) * PS4 + px0 + 64);
            ulonglong2 xA3 = *(const ulonglong2*)(xsb + (kc + 3) * PS4 + px0);
            ulonglong2 xB3 = *(const ulonglong2*)(xsb + (kc + 3) * PS4 + px0 + 64);
            #pragma unroll
            for (int u = 0; u < 4; ++u) {
                float4 wv = __ldg((const float4*)(wb3 + (oc0 + u) * Cc + kc));
                u64 w0 = splat2(wv.x), w1s = splat2(wv.y);
                u64 w2s = splat2(wv.z), w3s = splat2(wv.w);
                ffma2(a1[u][0], w0, xA0.x);  ffma2(a1[u][1], w0, xA0.y);
                ffma2(a1[u][2], w0, xB0.x);  ffma2(a1[u][3], w0, xB0.y);
                ffma2(a1[u][0], w1s, xA1.x); ffma2(a1[u][1], w1s, xA1.y);
                ffma2(a1[u][2], w1s, xB1.x); ffma2(a1[u][3], w1s, xB1.y);
                ffma2(a1[u][0], w2s, xA2.x); ffma2(a1[u][1], w2s, xA2.y);
                ffma2(a1[u][2], w2s, xB2.x); ffma2(a1[u][3], w2s, xB2.y);
                ffma2(a1[u][0], w3s, xA3.x); ffma2(a1[u][1], w3s, xA3.y);
                ffma2(a1[u][2], w3s, xB3.x); ffma2(a1[u][3], w3s, xB3.y);
            }
        }
        #pragma unroll
        for (int u = 0; u < 4; ++u) {
            int o = oc0 + u;
            float bt = __ldg(&beta[o]);
            float bias = __ldg(&b3[o]);
            float2 p0 = unpack2(a1[u][0]), p1 = unpack2(a1[u][1]);
            float2 p2 = unpack2(a1[u][2]), p3 = unpack2(a1[u][3]);
            float4* yv0 = (float4*)(ysb + o * PS4 + px0);
            float4 y0 = *yv0;
            y0.x += (p0.x + bias) * bt;
            y0.y += (p0.y + bias) * bt;
            y0.z += (p1.x + bias) * bt;
            y0.w += (p1.y + bias) * bt;
            *yv0 = y0;
            float4* yv1 = (float4*)(ysb + o * PS4 + px0 + 64);
            float4 y1 = *yv1;
            y1.x += (p2.x + bias) * bt;
            y1.y += (p2.y + bias) * bt;
            y1.z += (p3.x + bias) * bt;
            y1.w += (p3.y + bias) * bt;
            *yv1 = y1;
        }
    }
    __syncthreads();

    // LN2 (conflict-free): thread -> pixel p = t&127, half hh = t>>7 (32 channels).
    // Output -> xsb (dead after matvec1).
    {
        int p = t & 127, hh = t >> 7;
        float s = 0.f, qs = 0.f;
        #pragma unroll
        for (int c = 0; c < 32; ++c) {
            float v = ysb[(hh * 32 + c) * PS4 + p];
            s += v; qs += v * v;
        }
        sred[t] = s; qred[t] = qs;
        __syncthreads();
        if (t < 128) {
            float S = sred[t] + sred[t + 128];
            float Q = qred[t] + qred[t + 128];
            float mean = S * (1.f / 64.f);
            float var  = Q * (1.f / 64.f) - mean * mean;
            smean[t] = mean;
            sinv[t]  = rsqrtf(var + EPSv);
        }
        __syncthreads();
        float mean = smean[p], inv = sinv[p];
        #pragma unroll
        for (int c = 0; c < 32; ++c) {
            int ch = hh * 32 + c;
            float v = ysb[ch * PS4 + p];
            xsb[ch * PS4 + p] = (v - mean) * inv * lnws[ch] + lnbs[ch];
        }
    }
    __syncthreads();

    // matvec2: conv4 (128x64) + simple_gate. oc = tg + 16*j keeps gate pairs in-thread.
    {
        u64 a2[8][4];
        #pragma unroll
        for (int j = 0; j < 8; ++j)
            #pragma unroll
            for (int v = 0; v < 4; ++v) a2[j][v] = 0ull;
        for (int kc = 0; kc < 64; kc += 4) {
            ulonglong2 zA0 = *(const ulonglong2*)(xsb + (kc + 0) * PS4 + px0);
            ulonglong2 zB0 = *(const ulonglong2*)(xsb + (kc + 0) * PS4 + px0 + 64);
            ulonglong2 zA1 = *(const ulonglong2*)(xsb + (kc + 1) * PS4 + px0);
            ulonglong2 zB1 = *(const ulonglong2*)(xsb + (kc + 1) * PS4 + px0 + 64);
            ulonglong2 zA2 = *(const ulonglong2*)(xsb + (kc + 2) * PS4 + px0);
            ulonglong2 zB2 = *(const ulonglong2*)(xsb + (kc + 2) * PS4 + px0 + 64);
            ulonglong2 zA3 = *(const ulonglong2*)(xsb + (kc + 3) * PS4 + px0);
            ulonglong2 zB3 = *(const ulonglong2*)(xsb + (kc + 3) * PS4 + px0 + 64);
            #pragma unroll
            for (int j = 0; j < 8; ++j) {
                float4 wv = __ldg((const float4*)(wb4 + (tg + 16 * j) * Cc + kc));
                u64 w0 = splat2(wv.x), w1s = splat2(wv.y);
                u64 w2s = splat2(wv.z), w3s = splat2(wv.w);
                ffma2(a2[j][0], w0, zA0.x);  ffma2(a2[j][1], w0, zA0.y);
                ffma2(a2[j][2], w0, zB0.x);  ffma2(a2[j][3], w0, zB0.y);
                ffma2(a2[j][0], w1s, zA1.x); ffma2(a2[j][1], w1s, zA1.y);
                ffma2(a2[j][2], w1s, zB1.x); ffma2(a2[j][3], w1s, zB1.y);
                ffma2(a2[j][0], w2s, zA2.x); ffma2(a2[j][1], w2s, zA2.y);
                ffma2(a2[j][2], w2s, zB2.x); ffma2(a2[j][3], w2s, zB2.y);
                ffma2(a2[j][0], w3s, zA3.x); ffma2(a2[j][1], w3s, zA3.y);
                ffma2(a2[j][2], w3s, zB3.x); ffma2(a2[j][3], w3s, zB3.y);
            }
        }
        #pragma unroll
        for (int j = 0; j < 4; ++j) {
            int o = tg + 16 * j;
            u64 bl = splat2(__ldg(&b4[o]));
            u64 bh = splat2(__ldg(&b4[o + 64]));
            ulonglong2 gv0, gv1;
            gv0.x = mul2(add2(a2[j][0], bl), add2(a2[j + 4][0], bh));
            gv0.y = mul2(add2(a2[j][1], bl), add2(a2[j + 4][1], bh));
            gv1.x = mul2(add2(a2[j][2], bl), add2(a2[j + 4][2], bh));
            gv1.y = mul2(add2(a2[j][3], bl), add2(a2[j + 4][3], bh));
            *(ulonglong2*)(gsb + o * PS4 + px0)      = gv0;
            *(ulonglong2*)(gsb + o * PS4 + px0 + 64) = gv1;
        }
    }
    __syncthreads();

    // matvec3: conv5 (64x64);  out = y + (t5+bias)*gamma
    {
        int oc0 = tg * 4;
        u64 a3[4][4];
        #pragma unroll
        for (int u = 0; u < 4; ++u)
            #pragma unroll
            for (int v = 0; v < 4; ++v) a3[u][v] = 0ull;
        for (int kc = 0; kc < 64; kc += 4) {
            ulonglong2 gA0 = *(const ulonglong2*)(gsb + (kc + 0) * PS4 + px0);
            ulonglong2 gB0 = *(const ulonglong2*)(gsb + (kc + 0) * PS4 + px0 + 64);
            ulonglong2 gA1 = *(const ulonglong2*)(gsb + (kc + 1) * PS4 + px0);
            ulonglong2 gB1 = *(const ulonglong2*)(gsb + (kc + 1) * PS4 + px0 + 64);
            ulonglong2 gA2 = *(const ulonglong2*)(gsb + (kc + 2) * PS4 + px0);
            ulonglong2 gB2 = *(const ulonglong2*)(gsb + (kc + 2) * PS4 + px0 + 64);
            ulonglong2 gA3 = *(const ulonglong2*)(gsb + (kc + 3) * PS4 + px0);
            ulonglong2 gB3 = *(const ulonglong2*)(gsb + (kc + 3) * PS4 + px0 + 64);
            #pragma unroll
            for (int u = 0; u < 4; ++u) {
                float4 wv = __ldg((const float4*)(wb5 + (oc0 + u) * Cc + kc));
                u64 w0 = splat2(wv.x), w1s = splat2(wv.y);
                u64 w2s = splat2(wv.z), w3s = splat2(wv.w);
                ffma2(a3[u][0], w0, gA0.x);  ffma2(a3[u][1], w0, gA0.y);
                ffma2(a3[u][2], w0, gB0.x);  ffma2(a3[u][3], w0, gB0.y);
                ffma2(a3[u][0], w1s, gA1.x); ffma2(a3[u][1], w1s, gA1.y);
                ffma2(a3[u][2], w1s, gB1.x); ffma2(a3[u][3], w1s, gB1.y);
                ffma2(a3[u][0], w2s, gA2.x); ffma2(a3[u][1], w2s, gA2.y);
                ffma2(a3[u][2], w2s, gB2.x); ffma2(a3[u][3], w2s, gB2.y);
                ffma2(a3[u][0], w3s, gA3.x); ffma2(a3[u][1], w3s, gA3.y);
                ffma2(a3[u][2], w3s, gB3.x); ffma2(a3[u][3], w3s, gB3.y);
            }
        }
        float* ob = out + b * Cc * HWp + pix0 + px0;
        #pragma unroll
        for (int u = 0; u < 4; ++u) {
            int o = oc0 + u;
            float gm = __ldg(&gamma[o]);
            float bias = __ldg(&b5[o]);
            float2 p0 = unpack2(a3[u][0]), p1 = unpack2(a3[u][1]);
            float2 p2 = unpack2(a3[u][2]), p3 = unpack2(a3[u][3]);
            float4 yv0 = *(const float4*)(ysb + o * PS4 + px0);
            float4 r0;
            r0.x = yv0.x + (p0.x + bias) * gm;
            r0.y = yv0.y + (p0.y + bias) * gm;
            r0.z = yv0.z + (p1.x + bias) * gm;
            r0.w = yv0.w + (p1.y + bias) * gm;
            *(float4*)(ob + o * HWp) = r0;
            float4 yv1 = *(const float4*)(ysb + o * PS4 + px0 + 64);
            float4 r1;
            r1.x = yv1.x + (p2.x + bias) * gm;
            r1.y = yv1.y + (p2.y + bias) * gm;
            r1.z = yv1.z + (p3.x + bias) * gm;
            r1.w = yv1.w + (p3.y + bias) * gm;
            *(float4*)(ob + o * HWp + 64) = r1;
        }
    }
}

// ---------------- launch ----------------
extern "C" void kernel_launch(void* const* d_in, const int* in_sizes, int n_in,
                              void* d_out, int out_size) {
    const float* inp   = (const float*)d_in[0];
    const float* probs = (const float*)d_in[1];
    const float* ln1w  = (const float*)d_in[2];
    const float* ln1b  = (const float*)d_in[3];
    const float* ln2w  = (const float*)d_in[4];
    const float* ln2b  = (const float*)d_in[5];
    const float* w1    = (const float*)d_in[6];
    const float* b1    = (const float*)d_in[7];
    const float* la1   = (const float*)d_in[8];
    const float* lb1   = (const float*)d_in[9];
    const float* w2    = (const float*)d_in[10];
    const float* b2    = (const float*)d_in[11];
    const float* la2   = (const float*)d_in[12];
    const float* lb2   = (const float*)d_in[13];
    const float* wsca  = (const float*)d_in[14];
    const float* bsca  = (const float*)d_in[15];
    const float* lasca = (const float*)d_in[16];
    const float* lbsca = (const float*)d_in[17];
    const float* w3    = (const float*)d_in[18];
    const float* b3    = (const float*)d_in[19];
    const float* la3   = (const float*)d_in[20];
    const float* lb3   = (const float*)d_in[21];
    const float* w4    = (const float*)d_in[22];
    const float* b4    = (const float*)d_in[23];
    const float* la4   = (const float*)d_in[24];
    const float* lb4   = (const float*)d_in[25];
    const float* w5    = (const float*)d_in[26];
    const float* b5    = (const float*)d_in[27];
    const float* la5   = (const float*)d_in[28];
    const float* lb5   = (const float*)d_in[29];
    const float* beta  = (const float*)d_in[30];
    const float* gamma = (const float*)d_in[31];
    float* out = (float*)d_out;

    const int SM4 = (3 * 64 * PS4) * (int)sizeof(float);   // 101,376
    cudaFuncSetAttribute(k4_kernel, cudaFuncAttributeMaxDynamicSharedMemorySize, SM4);

    k_weights<<<dim3(6, Bn), 256>>>(probs,
                                    w1, la1, lb1, w2, la2, lb2,
                                    wsca, lasca, lbsca, w3, la3, lb3,
                                    w4, la4, lb4, w5, la5, lb5);
    k1_kernel<<<dim3(HWp / 128, Bn), 256>>>(inp, ln1w, ln1b, b1);
    k2_kernel<<<dim3(Hh / 4, Cc, Bn), 256>>>(b2);
    k4_kernel<<<dim3(HWp / 128, Bn), 256, SM4>>>(inp, ln2w, ln2b, bsca, b3, b4, b5, beta, gamma, out);
}